// round 4
// baseline (speedup 1.0000x reference)
#include <cuda_runtime.h>
#include <cuda_bf16.h>
#include <math_constants.h>
#include <cstdint>

#define BATCH  8
#define SLEN   1024
#define NHEAD  8
#define DMODEL 512
#define DKV    64
#define MROWS  (BATCH * SLEN)   // 8192
#define WSZ    (DMODEL * DMODEL)

// ---------------------------------------------------------------------------
// Scratch (allocation-free: __device__ globals)
// ---------------------------------------------------------------------------
__device__ __nv_bfloat16 g_ah[MROWS * DMODEL];      // A hi (inputs, later ctx)
__device__ __nv_bfloat16 g_al[MROWS * DMODEL];      // A lo
__device__ __nv_bfloat16 g_wh[4 * WSZ];             // wq|wk|wv|wo hi
__device__ __nv_bfloat16 g_wl[4 * WSZ];             // wq|wk|wv|wo lo
__device__ __nv_bfloat16 g_qh[MROWS * DMODEL], g_ql[MROWS * DMODEL];  // [b,h,s,d]
__device__ __nv_bfloat16 g_kh[MROWS * DMODEL], g_kl[MROWS * DMODEL];
__device__ __nv_bfloat16 g_vh[MROWS * DMODEL], g_vl[MROWS * DMODEL];
__device__ uint32_t g_mbits[BATCH * SLEN * (SLEN / 32)];   // 1MB bitmask

// ---------------------------------------------------------------------------
// Baseline-ISA helpers (sm_80-era: survive the harness's plain sm_103 target)
// ---------------------------------------------------------------------------
__device__ __forceinline__ uint32_t smem_u32(const void* p) {
    uint32_t a;
    asm("{ .reg .u64 t; cvta.to.shared.u64 t, %1; cvt.u32.u64 %0, t; }" : "=r"(a) : "l"(p));
    return a;
}
__device__ __forceinline__ void ldsm_x4(uint32_t& r0, uint32_t& r1, uint32_t& r2,
                                        uint32_t& r3, uint32_t addr) {
    asm volatile("ldmatrix.sync.aligned.m8n8.x4.shared.b16 {%0,%1,%2,%3}, [%4];"
                 : "=r"(r0), "=r"(r1), "=r"(r2), "=r"(r3) : "r"(addr));
}
__device__ __forceinline__ void ldsm_x4t(uint32_t& r0, uint32_t& r1, uint32_t& r2,
                                         uint32_t& r3, uint32_t addr) {
    asm volatile("ldmatrix.sync.aligned.m8n8.x4.trans.shared.b16 {%0,%1,%2,%3}, [%4];"
                 : "=r"(r0), "=r"(r1), "=r"(r2), "=r"(r3) : "r"(addr));
}
__device__ __forceinline__ void mma_bf16(float* c, uint32_t a0, uint32_t a1, uint32_t a2,
                                         uint32_t a3, uint32_t b0, uint32_t b1) {
    asm volatile("mma.sync.aligned.m16n8k16.row.col.f32.bf16.bf16.f32 "
                 "{%0,%1,%2,%3}, {%4,%5,%6,%7}, {%8,%9}, {%0,%1,%2,%3};"
                 : "+f"(c[0]), "+f"(c[1]), "+f"(c[2]), "+f"(c[3])
                 : "r"(a0), "r"(a1), "r"(a2), "r"(a3), "r"(b0), "r"(b1));
}
__device__ __forceinline__ void cpa16(uint32_t s, const void* g) {
    asm volatile("cp.async.cg.shared.global [%0], [%1], 16;" :: "r"(s), "l"(g));
}
#define CPA_COMMIT() asm volatile("cp.async.commit_group;" ::: "memory")
#define CPA_WAIT0()  asm volatile("cp.async.wait_group 0;" ::: "memory")

__device__ __forceinline__ uint32_t pack2h(__nv_bfloat16 lo, __nv_bfloat16 hi) {
    return ((uint32_t)__bfloat16_as_ushort(hi) << 16) | __bfloat16_as_ushort(lo);
}
__device__ __forceinline__ void split2(float x, float y, uint32_t& hp, uint32_t& lp) {
    __nv_bfloat16 hx = __float2bfloat16(x), hy = __float2bfloat16(y);
    hp = pack2h(hx, hy);
    lp = pack2h(__float2bfloat16(x - __bfloat162float(hx)),
                __float2bfloat16(y - __bfloat162float(hy)));
}

// ---------------------------------------------------------------------------
// fp32 -> bf16 hi/lo split (inputs / ctx)
// ---------------------------------------------------------------------------
__global__ __launch_bounds__(256) void cvt_kernel(
    const float* __restrict__ src, __nv_bfloat16* __restrict__ hi,
    __nv_bfloat16* __restrict__ lo, int n4)
{
    int i = blockIdx.x * 256 + threadIdx.x;
    if (i >= n4) return;
    float4 v = ((const float4*)src)[i];
    uint32_t h0, l0, h1, l1;
    split2(v.x, v.y, h0, l0);
    split2(v.z, v.w, h1, l1);
    ((uint2*)hi)[i] = make_uint2(h0, h1);
    ((uint2*)lo)[i] = make_uint2(l0, l1);
}

// All 4 weight matrices in one launch (z selects)
__global__ __launch_bounds__(256) void cvt_w_kernel(
    const float* __restrict__ w0, const float* __restrict__ w1,
    const float* __restrict__ w2, const float* __restrict__ w3)
{
    int z = blockIdx.z;
    const float* src = (z == 0) ? w0 : (z == 1) ? w1 : (z == 2) ? w2 : w3;
    __nv_bfloat16* hi = g_wh + (size_t)z * WSZ;
    __nv_bfloat16* lo = g_wl + (size_t)z * WSZ;
    int i = blockIdx.x * 256 + threadIdx.x;
    if (i >= WSZ / 4) return;
    float4 v = ((const float4*)src)[i];
    uint32_t h0, l0, h1, l1;
    split2(v.x, v.y, h0, l0);
    split2(v.z, v.w, h1, l1);
    ((uint2*)hi)[i] = make_uint2(h0, h1);
    ((uint2*)lo)[i] = make_uint2(l0, l1);
}

// mask (fp32, !=0 means masked) -> bitmask words
__global__ __launch_bounds__(256) void maskbits_kernel(const float* __restrict__ mask, int nwords)
{
    int gw = (blockIdx.x * blockDim.x + threadIdx.x) >> 5;
    int lane = threadIdx.x & 31;
    int nw = (gridDim.x * blockDim.x) >> 5;
    for (int w = gw; w < nwords; w += nw) {
        float v = mask[(size_t)w * 32 + lane];
        uint32_t bits = __ballot_sync(0xffffffffu, v != 0.f);
        if (lane == 0) g_mbits[w] = bits;
    }
}

// ---------------------------------------------------------------------------
// bf16-split GEMM via mma.sync: C[8192,512] = A @ W^T + bias
// block 128x128, 8 warps, KC=32, cp.async double buffer.
// QKV=true: gridDim.z=3 selects wq/wk/wv, scatter bf16 hi/lo to g_{q,k,v}.
// QKV=false: single W, fp32 row-major out.
// ---------------------------------------------------------------------------
#define GKC 32
#define GROWB 80
#define GA_BYTES (128 * GROWB)
#define GBUF (4 * GA_BYTES)
#define GEMM_SMEM (2 * GBUF)        // 81920

template <bool QKV>
__global__ __launch_bounds__(256) void mm_kernel(
    const __nv_bfloat16* __restrict__ Ah, const __nv_bfloat16* __restrict__ Al,
    const __nv_bfloat16* __restrict__ Whb, const __nv_bfloat16* __restrict__ Wlb,
    const float* __restrict__ b0a, const float* __restrict__ b1a,
    const float* __restrict__ b2a, float* __restrict__ Cout)
{
    extern __shared__ char smem[];
    const uint32_t sb = smem_u32(smem);
    const int tid = threadIdx.x, lane = tid & 31, wid = tid >> 5;
    const int wm = wid >> 1, wn = wid & 1;
    const int bm = blockIdx.y * 128, bn = blockIdx.x * 128;
    const int z = QKV ? blockIdx.z : 0;

    const __nv_bfloat16* Bh = Whb + (size_t)z * WSZ;
    const __nv_bfloat16* Bl = Wlb + (size_t)z * WSZ;
    const float* bias = QKV ? ((z == 0) ? b0a : (z == 1) ? b1a : b2a) : b0a;

    float acc[2][8][4];
#pragma unroll
    for (int i = 0; i < 2; i++)
#pragma unroll
        for (int j = 0; j < 8; j++)
#pragma unroll
            for (int k = 0; k < 4; k++) acc[i][j][k] = 0.f;

    auto load_chunk = [&](int c, int st) {
        uint32_t dst = sb + st * GBUF;
        int k0 = c * GKC;
        const __nv_bfloat16* srcs[4] = {Ah, Al, Bh, Bl};
#pragma unroll
        for (int arr = 0; arr < 4; arr++) {
            int rb = (arr < 2) ? bm : bn;
            const __nv_bfloat16* S = srcs[arr];
#pragma unroll
            for (int it = 0; it < 2; it++) {
                int idx = tid + it * 256;
                int r = idx >> 2, cc = idx & 3;
                cpa16(dst + arr * GA_BYTES + r * GROWB + cc * 16,
                      S + (size_t)(rb + r) * DMODEL + k0 + cc * 8);
            }
        }
        CPA_COMMIT();
    };

    load_chunk(0, 0);
    CPA_WAIT0();
    __syncthreads();

    for (int c = 0; c < DMODEL / GKC; ++c) {
        int st = c & 1;
        if (c < DMODEL / GKC - 1) load_chunk(c + 1, st ^ 1);
        uint32_t base = sb + st * GBUF;

        uint32_t ah[2][2][4], al[2][2][4];
#pragma unroll
        for (int mf = 0; mf < 2; mf++)
#pragma unroll
            for (int ks = 0; ks < 2; ks++) {
                uint32_t row = wm * 32 + mf * 16 + (lane & 15);
                uint32_t col = ks * 32 + ((lane >> 4) << 4);
                ldsm_x4(ah[mf][ks][0], ah[mf][ks][1], ah[mf][ks][2], ah[mf][ks][3],
                        base + 0 * GA_BYTES + row * GROWB + col);
                ldsm_x4(al[mf][ks][0], al[mf][ks][1], al[mf][ks][2], al[mf][ks][3],
                        base + 1 * GA_BYTES + row * GROWB + col);
            }
#pragma unroll
        for (int nf = 0; nf < 8; nf++) {
            uint32_t row = wn * 64 + nf * 8 + (lane & 7);
            uint32_t col = (lane >> 3) << 4;
            uint32_t bh[4], bl[4];
            ldsm_x4(bh[0], bh[1], bh[2], bh[3], base + 2 * GA_BYTES + row * GROWB + col);
            ldsm_x4(bl[0], bl[1], bl[2], bl[3], base + 3 * GA_BYTES + row * GROWB + col);
#pragma unroll
            for (int ks = 0; ks < 2; ks++)
#pragma unroll
                for (int mf = 0; mf < 2; mf++) {
                    float* C = acc[mf][nf];
                    mma_bf16(C, ah[mf][ks][0], ah[mf][ks][1], ah[mf][ks][2], ah[mf][ks][3],
                             bh[2 * ks], bh[2 * ks + 1]);
                    mma_bf16(C, ah[mf][ks][0], ah[mf][ks][1], ah[mf][ks][2], ah[mf][ks][3],
                             bl[2 * ks], bl[2 * ks + 1]);
                    mma_bf16(C, al[mf][ks][0], al[mf][ks][1], al[mf][ks][2], al[mf][ks][3],
                             bh[2 * ks], bh[2 * ks + 1]);
                }
        }
        if (c < DMODEL / GKC - 1) CPA_WAIT0();
        __syncthreads();
    }

    const int q4 = lane & 3, r4 = lane >> 2;
#pragma unroll
    for (int mf = 0; mf < 2; mf++)
#pragma unroll
        for (int nf = 0; nf < 8; nf++) {
            int col = bn + wn * 64 + nf * 8 + q4 * 2;
            float2 bb = *(const float2*)(bias + col);
#pragma unroll
            for (int hh = 0; hh < 2; hh++) {
                int row = bm + wm * 32 + mf * 16 + r4 + hh * 8;
                float v0 = acc[mf][nf][2 * hh + 0] + bb.x;
                float v1 = acc[mf][nf][2 * hh + 1] + bb.y;
                if (!QKV) {
                    *(float2*)(Cout + (size_t)row * DMODEL + col) = make_float2(v0, v1);
                } else {
                    int b = row >> 10, s = row & 1023, hd = col >> 6, d = col & 63;
                    size_t o = ((size_t)((b * NHEAD + hd) * SLEN + s)) * DKV + d;
                    uint32_t hp, lp;
                    split2(v0, v1, hp, lp);
                    __nv_bfloat16* dh = (z == 0) ? g_qh : (z == 1) ? g_kh : g_vh;
                    __nv_bfloat16* dl = (z == 0) ? g_ql : (z == 1) ? g_kl : g_vl;
                    *(uint32_t*)(dh + o) = hp;
                    *(uint32_t*)(dl + o) = lp;
                }
            }
        }
}

// ---------------------------------------------------------------------------
// Flash attention via mma.sync, bf16 hi/lo split for QK^T and PV.
// Block: 128 q-rows x one (b,h). 8 warps, 16 q-rows each, full 64-col tiles.
// ---------------------------------------------------------------------------
#define AROWB 144
#define AT_BYTES (64 * AROWB)        // 9216
#define ABUF (4 * AT_BYTES)          // Kh,Kl,Vh,Vl = 36864 per stage
#define ATTN_SMEM (2 * ABUF)         // 73728

__global__ __launch_bounds__(256) void attn_kernel()
{
    extern __shared__ char smem[];
    const uint32_t sb = smem_u32(smem);
    const int tid = threadIdx.x, lane = tid & 31, w = tid >> 5;
    const int q4 = lane & 3, r4 = lane >> 2;
    const int qt = blockIdx.x, bh = blockIdx.y;
    const int b = bh >> 3, h = bh & 7;

    const __nv_bfloat16* Qh = g_qh + (size_t)bh * SLEN * DKV + (size_t)qt * 128 * DKV;
    const __nv_bfloat16* Ql = g_ql + (size_t)bh * SLEN * DKV + (size_t)qt * 128 * DKV;
    const __nv_bfloat16* Kh = g_kh + (size_t)bh * SLEN * DKV;
    const __nv_bfloat16* Kl = g_kl + (size_t)bh * SLEN * DKV;
    const __nv_bfloat16* Vh = g_vh + (size_t)bh * SLEN * DKV;
    const __nv_bfloat16* Vl = g_vl + (size_t)bh * SLEN * DKV;

    // ---- stage 128-row Q (hi,lo) into buffer 1, extract fragments ----
    {
        uint32_t qb = sb + ABUF;
#pragma unroll
        for (int arr = 0; arr < 2; arr++) {
            const __nv_bfloat16* S = arr ? Ql : Qh;
#pragma unroll
            for (int it = 0; it < 4; it++) {
                int idx = tid + it * 256;       // 0..1023
                int r = idx >> 3, cc = idx & 7;
                cpa16(qb + arr * (2 * AT_BYTES) + r * AROWB + cc * 16, S + r * DKV + cc * 8);
            }
        }
        CPA_COMMIT();
        CPA_WAIT0();
        __syncthreads();
    }
    uint32_t qfh[4][4], qfl[4][4];
    {
        uint32_t qb = sb + ABUF;
        uint32_t row = w * 16 + (lane & 15);
#pragma unroll
        for (int ks = 0; ks < 4; ks++) {
            uint32_t col = ks * 32 + ((lane >> 4) << 4);
            ldsm_x4(qfh[ks][0], qfh[ks][1], qfh[ks][2], qfh[ks][3],
                    qb + row * AROWB + col);
            ldsm_x4(qfl[ks][0], qfl[ks][1], qfl[ks][2], qfl[ks][3],
                    qb + 2 * AT_BYTES + row * AROWB + col);
        }
    }

    auto load_tile = [&](int kt, int st) {
        uint32_t dst = sb + st * ABUF;
        const __nv_bfloat16* srcs[4] = {Kh + (size_t)kt * 64 * DKV, Kl + (size_t)kt * 64 * DKV,
                                        Vh + (size_t)kt * 64 * DKV, Vl + (size_t)kt * 64 * DKV};
#pragma unroll
        for (int arr = 0; arr < 4; arr++)
#pragma unroll
            for (int it = 0; it < 2; it++) {
                int idx = tid + it * 256;       // 0..511
                int r = idx >> 3, cc = idx & 7;
                cpa16(dst + arr * AT_BYTES + r * AROWB + cc * 16, srcs[arr] + r * DKV + cc * 8);
            }
        CPA_COMMIT();
    };

    load_tile(0, 0);     // buffer 0 (Q lives in buffer 1; disjoint)
    CPA_WAIT0();
    __syncthreads();     // orders Q-frag reads before tile 1 overwrites buf 1

    float o[8][4];
#pragma unroll
    for (int j = 0; j < 8; j++)
#pragma unroll
        for (int k = 0; k < 4; k++) o[j][k] = 0.f;
    float m0 = -1e30f, m1 = -1e30f, l0 = 0.f, l1 = 0.f;

    const uint32_t* mrow0 = g_mbits + ((size_t)b * SLEN + qt * 128 + w * 16 + r4) * 32;
    const uint32_t* mrow1 = mrow0 + 8 * 32;

    for (int kt = 0; kt < 16; ++kt) {
        int st = kt & 1;
        if (kt < 15) load_tile(kt + 1, st ^ 1);
        uint32_t base = sb + st * ABUF;

        // ---- S = Q @ K^T (fp32 accum, 3-way split) ----
        float s[8][4];
#pragma unroll
        for (int j = 0; j < 8; j++)
#pragma unroll
            for (int k = 0; k < 4; k++) s[j][k] = 0.f;

#pragma unroll
        for (int nf = 0; nf < 8; nf++) {
            uint32_t row = nf * 8 + (lane & 7);
            uint32_t coff = (lane >> 3) << 4;
            uint32_t kh0[4], kh1[4], kl0[4], kl1[4];
            ldsm_x4(kh0[0], kh0[1], kh0[2], kh0[3], base + 0 * AT_BYTES + row * AROWB + coff);
            ldsm_x4(kh1[0], kh1[1], kh1[2], kh1[3], base + 0 * AT_BYTES + row * AROWB + 64 + coff);
            ldsm_x4(kl0[0], kl0[1], kl0[2], kl0[3], base + 1 * AT_BYTES + row * AROWB + coff);
            ldsm_x4(kl1[0], kl1[1], kl1[2], kl1[3], base + 1 * AT_BYTES + row * AROWB + 64 + coff);
#pragma unroll
            for (int ks = 0; ks < 4; ks++) {
                uint32_t* KH = (ks < 2) ? kh0 : kh1;
                uint32_t* KL = (ks < 2) ? kl0 : kl1;
                int kk = (ks & 1) * 2;
                mma_bf16(s[nf], qfh[ks][0], qfh[ks][1], qfh[ks][2], qfh[ks][3], KH[kk], KH[kk + 1]);
                mma_bf16(s[nf], qfh[ks][0], qfh[ks][1], qfh[ks][2], qfh[ks][3], KL[kk], KL[kk + 1]);
                mma_bf16(s[nf], qfl[ks][0], qfl[ks][1], qfl[ks][2], qfl[ks][3], KH[kk], KH[kk + 1]);
            }
        }

        // ---- mask + scale ----
        uint32_t w0a = mrow0[kt * 2], w0b = mrow0[kt * 2 + 1];
        uint32_t w1a = mrow1[kt * 2], w1b = mrow1[kt * 2 + 1];
        float rm0 = -CUDART_INF_F, rm1 = -CUDART_INF_F;
#pragma unroll
        for (int nf = 0; nf < 8; nf++) {
            int c = nf * 8 + q4 * 2;
            uint32_t wr0 = (c < 32) ? w0a : w0b;
            uint32_t wr1 = (c < 32) ? w1a : w1b;
            int sh = c & 31;
            s[nf][0] = ((wr0 >> sh) & 1) ? -CUDART_INF_F : s[nf][0] * 0.125f;
            s[nf][1] = ((wr0 >> (sh + 1)) & 1) ? -CUDART_INF_F : s[nf][1] * 0.125f;
            s[nf][2] = ((wr1 >> sh) & 1) ? -CUDART_INF_F : s[nf][2] * 0.125f;
            s[nf][3] = ((wr1 >> (sh + 1)) & 1) ? -CUDART_INF_F : s[nf][3] * 0.125f;
            rm0 = fmaxf(rm0, fmaxf(s[nf][0], s[nf][1]));
            rm1 = fmaxf(rm1, fmaxf(s[nf][2], s[nf][3]));
        }
        rm0 = fmaxf(rm0, __shfl_xor_sync(0xffffffffu, rm0, 1));
        rm0 = fmaxf(rm0, __shfl_xor_sync(0xffffffffu, rm0, 2));
        rm1 = fmaxf(rm1, __shfl_xor_sync(0xffffffffu, rm1, 1));
        rm1 = fmaxf(rm1, __shfl_xor_sync(0xffffffffu, rm1, 2));

        float mn0 = fmaxf(m0, rm0), mn1 = fmaxf(m1, rm1);
        float sc0 = __expf(m0 - mn0), sc1 = __expf(m1 - mn1);
        float rs0 = 0.f, rs1 = 0.f;
        uint32_t pH01[8], pH23[8], pL01[8], pL23[8];
#pragma unroll
        for (int nf = 0; nf < 8; nf++) {
            float p0 = __expf(s[nf][0] - mn0);
            float p1 = __expf(s[nf][1] - mn0);
            float p2 = __expf(s[nf][2] - mn1);
            float p3 = __expf(s[nf][3] - mn1);
            rs0 += p0 + p1;
            rs1 += p2 + p3;
            split2(p0, p1, pH01[nf], pL01[nf]);
            split2(p2, p3, pH23[nf], pL23[nf]);
        }
        rs0 += __shfl_xor_sync(0xffffffffu, rs0, 1);
        rs0 += __shfl_xor_sync(0xffffffffu, rs0, 2);
        rs1 += __shfl_xor_sync(0xffffffffu, rs1, 1);
        rs1 += __shfl_xor_sync(0xffffffffu, rs1, 2);
        l0 = l0 * sc0 + rs0;
        l1 = l1 * sc1 + rs1;
        m0 = mn0;
        m1 = mn1;
#pragma unroll
        for (int nf = 0; nf < 8; nf++) {
            o[nf][0] *= sc0;
            o[nf][1] *= sc0;
            o[nf][2] *= sc1;
            o[nf][3] *= sc1;
        }

        // ---- O += P @ V  (P frags in registers; V via ldmatrix.x4.trans) ----
#pragma unroll
        for (int ks = 0; ks < 4; ks++) {
            uint32_t a0 = pH01[2 * ks], a1 = pH23[2 * ks];
            uint32_t a2 = pH01[2 * ks + 1], a3 = pH23[2 * ks + 1];
            uint32_t la0 = pL01[2 * ks], la1 = pL23[2 * ks];
            uint32_t la2 = pL01[2 * ks + 1], la3 = pL23[2 * ks + 1];
            uint32_t vaddr = (ks * 16 + (lane & 15)) * AROWB + ((lane >> 4) << 4);
#pragma unroll
            for (int nf2 = 0; nf2 < 4; nf2++) {
                uint32_t vh[4], vl[4];
                ldsm_x4t(vh[0], vh[1], vh[2], vh[3], base + 2 * AT_BYTES + vaddr + nf2 * 32);
                ldsm_x4t(vl[0], vl[1], vl[2], vl[3], base + 3 * AT_BYTES + vaddr + nf2 * 32);
                mma_bf16(o[2 * nf2 + 0], a0, a1, a2, a3, vh[0], vh[1]);
                mma_bf16(o[2 * nf2 + 0], a0, a1, a2, a3, vl[0], vl[1]);
                mma_bf16(o[2 * nf2 + 0], la0, la1, la2, la3, vh[0], vh[1]);
                mma_bf16(o[2 * nf2 + 1], a0, a1, a2, a3, vh[2], vh[3]);
                mma_bf16(o[2 * nf2 + 1], a0, a1, a2, a3, vl[2], vl[3]);
                mma_bf16(o[2 * nf2 + 1], la0, la1, la2, la3, vh[2], vh[3]);
            }
        }

        if (kt < 15) CPA_WAIT0();
        __syncthreads();
    }

    // ---- epilogue: ctx = O / l -> bf16 hi/lo into g_ah/g_al ----
    float il0 = (l0 > 0.f) ? (1.f / l0) : 0.f;
    float il1 = (l1 > 0.f) ? (1.f / l1) : 0.f;
    int row0 = qt * 128 + w * 16 + r4;
#pragma unroll
    for (int nf = 0; nf < 8; nf++) {
        int col = h * 64 + nf * 8 + q4 * 2;
        uint32_t hp, lp;
        split2(o[nf][0] * il0, o[nf][1] * il0, hp, lp);
        *(uint32_t*)(g_ah + (size_t)(b * SLEN + row0) * DMODEL + col) = hp;
        *(uint32_t*)(g_al + (size_t)(b * SLEN + row0) * DMODEL + col) = lp;
        split2(o[nf][2] * il1, o[nf][3] * il1, hp, lp);
        *(uint32_t*)(g_ah + (size_t)(b * SLEN + row0 + 8) * DMODEL + col) = hp;
        *(uint32_t*)(g_al + (size_t)(b * SLEN + row0 + 8) * DMODEL + col) = lp;
    }
}

// ---------------------------------------------------------------------------
extern "C" void kernel_launch(void* const* d_in, const int* in_sizes, int n_in,
                              void* d_out, int out_size)
{
    const float* inputs = (const float*)d_in[0];
    const float* mask   = (const float*)d_in[1];
    const float* wq = (const float*)d_in[2];
    const float* bq = (const float*)d_in[3];
    const float* wk = (const float*)d_in[4];
    const float* bk = (const float*)d_in[5];
    const float* wv = (const float*)d_in[6];
    const float* bv = (const float*)d_in[7];
    const float* wo = (const float*)d_in[8];
    const float* bo = (const float*)d_in[9];
    float* out = (float*)d_out;

    __nv_bfloat16 *ah, *al, *wh, *wl;
    cudaGetSymbolAddress((void**)&ah, g_ah);
    cudaGetSymbolAddress((void**)&al, g_al);
    cudaGetSymbolAddress((void**)&wh, g_wh);
    cudaGetSymbolAddress((void**)&wl, g_wl);

    cvt_kernel<<<(MROWS * DMODEL / 4 + 255) / 256, 256>>>(inputs, ah, al, MROWS * DMODEL / 4);
    cvt_w_kernel<<<dim3((WSZ / 4 + 255) / 256, 1, 4), 256>>>(wq, wk, wv, wo);
    maskbits_kernel<<<256, 256>>>(mask, BATCH * SLEN * (SLEN / 32));

    cudaFuncSetAttribute(mm_kernel<true>, cudaFuncAttributeMaxDynamicSharedMemorySize, GEMM_SMEM);
    cudaFuncSetAttribute(mm_kernel<false>, cudaFuncAttributeMaxDynamicSharedMemorySize, GEMM_SMEM);
    cudaFuncSetAttribute(attn_kernel, cudaFuncAttributeMaxDynamicSharedMemorySize, ATTN_SMEM);

    dim3 gqkv(DMODEL / 128, MROWS / 128, 3);   // (4, 64, 3)
    mm_kernel<true><<<gqkv, 256, GEMM_SMEM>>>(ah, al, wh, wl, bq, bk, bv, nullptr);

    dim3 ga(SLEN / 128, BATCH * NHEAD);        // (8, 64)
    attn_kernel<<<ga, 256, ATTN_SMEM>>>();     // writes ctx hi/lo into g_ah/g_al

    dim3 go(DMODEL / 128, MROWS / 128);        // (4, 64)
    mm_kernel<false><<<go, 256, GEMM_SMEM>>>(ah, al, wh + 3 * WSZ, wl + 3 * WSZ,
                                             bo, nullptr, nullptr, out);
}

// round 5
// speedup vs baseline: 1.1128x; 1.1128x over previous
#include <cuda_runtime.h>
#include <cuda_bf16.h>
#include <math_constants.h>
#include <cstdint>

#define BATCH  8
#define SLEN   1024
#define NHEAD  8
#define DMODEL 512
#define DKV    64
#define MROWS  (BATCH * SLEN)   // 8192
#define WSZ    (DMODEL * DMODEL)

// ---------------------------------------------------------------------------
// Scratch (allocation-free: __device__ globals)
// ---------------------------------------------------------------------------
__device__ __nv_bfloat16 g_ah[MROWS * DMODEL];      // A hi (inputs, later ctx)
__device__ __nv_bfloat16 g_al[MROWS * DMODEL];      // A lo
__device__ __nv_bfloat16 g_wh[4 * WSZ];             // wq|wk|wv|wo hi
__device__ __nv_bfloat16 g_wl[4 * WSZ];             // wq|wk|wv|wo lo
__device__ __nv_bfloat16 g_qh[MROWS * DMODEL], g_ql[MROWS * DMODEL];  // [b,h,s,d]
__device__ __nv_bfloat16 g_kh[MROWS * DMODEL], g_kl[MROWS * DMODEL];
__device__ __nv_bfloat16 g_vh[MROWS * DMODEL], g_vl[MROWS * DMODEL];
__device__ uint32_t g_mbits[BATCH * SLEN * (SLEN / 32)];   // 1MB bitmask

// ---------------------------------------------------------------------------
// Baseline-ISA helpers (sm_80-era: survive the harness's plain sm_103 target)
// ---------------------------------------------------------------------------
__device__ __forceinline__ uint32_t smem_u32(const void* p) {
    uint32_t a;
    asm("{ .reg .u64 t; cvta.to.shared.u64 t, %1; cvt.u32.u64 %0, t; }" : "=r"(a) : "l"(p));
    return a;
}
__device__ __forceinline__ void ldsm_x4(uint32_t& r0, uint32_t& r1, uint32_t& r2,
                                        uint32_t& r3, uint32_t addr) {
    asm volatile("ldmatrix.sync.aligned.m8n8.x4.shared.b16 {%0,%1,%2,%3}, [%4];"
                 : "=r"(r0), "=r"(r1), "=r"(r2), "=r"(r3) : "r"(addr));
}
__device__ __forceinline__ void ldsm_x4t(uint32_t& r0, uint32_t& r1, uint32_t& r2,
                                         uint32_t& r3, uint32_t addr) {
    asm volatile("ldmatrix.sync.aligned.m8n8.x4.trans.shared.b16 {%0,%1,%2,%3}, [%4];"
                 : "=r"(r0), "=r"(r1), "=r"(r2), "=r"(r3) : "r"(addr));
}
__device__ __forceinline__ void mma_bf16(float* c, uint32_t a0, uint32_t a1, uint32_t a2,
                                         uint32_t a3, uint32_t b0, uint32_t b1) {
    asm volatile("mma.sync.aligned.m16n8k16.row.col.f32.bf16.bf16.f32 "
                 "{%0,%1,%2,%3}, {%4,%5,%6,%7}, {%8,%9}, {%0,%1,%2,%3};"
                 : "+f"(c[0]), "+f"(c[1]), "+f"(c[2]), "+f"(c[3])
                 : "r"(a0), "r"(a1), "r"(a2), "r"(a3), "r"(b0), "r"(b1));
}
__device__ __forceinline__ void cpa16(uint32_t s, const void* g) {
    asm volatile("cp.async.cg.shared.global [%0], [%1], 16;" :: "r"(s), "l"(g));
}
#define CPA_COMMIT() asm volatile("cp.async.commit_group;" ::: "memory")
#define CPA_WAIT0()  asm volatile("cp.async.wait_group 0;" ::: "memory")

__device__ __forceinline__ uint32_t pack2h(__nv_bfloat16 lo, __nv_bfloat16 hi) {
    return ((uint32_t)__bfloat16_as_ushort(hi) << 16) | __bfloat16_as_ushort(lo);
}
__device__ __forceinline__ void split2(float x, float y, uint32_t& hp, uint32_t& lp) {
    __nv_bfloat16 hx = __float2bfloat16(x), hy = __float2bfloat16(y);
    hp = pack2h(hx, hy);
    lp = pack2h(__float2bfloat16(x - __bfloat162float(hx)),
                __float2bfloat16(y - __bfloat162float(hy)));
}

// ---------------------------------------------------------------------------
// fp32 -> bf16 hi/lo split (inputs / ctx)
// ---------------------------------------------------------------------------
__global__ __launch_bounds__(256) void cvt_kernel(
    const float* __restrict__ src, __nv_bfloat16* __restrict__ hi,
    __nv_bfloat16* __restrict__ lo, int n4)
{
    int i = blockIdx.x * 256 + threadIdx.x;
    if (i >= n4) return;
    float4 v = ((const float4*)src)[i];
    uint32_t h0, l0, h1, l1;
    split2(v.x, v.y, h0, l0);
    split2(v.z, v.w, h1, l1);
    ((uint2*)hi)[i] = make_uint2(h0, h1);
    ((uint2*)lo)[i] = make_uint2(l0, l1);
}

// All 4 weight matrices in one launch (z selects)
__global__ __launch_bounds__(256) void cvt_w_kernel(
    const float* __restrict__ w0, const float* __restrict__ w1,
    const float* __restrict__ w2, const float* __restrict__ w3)
{
    int z = blockIdx.z;
    const float* src = (z == 0) ? w0 : (z == 1) ? w1 : (z == 2) ? w2 : w3;
    __nv_bfloat16* hi = g_wh + (size_t)z * WSZ;
    __nv_bfloat16* lo = g_wl + (size_t)z * WSZ;
    int i = blockIdx.x * 256 + threadIdx.x;
    if (i >= WSZ / 4) return;
    float4 v = ((const float4*)src)[i];
    uint32_t h0, l0, h1, l1;
    split2(v.x, v.y, h0, l0);
    split2(v.z, v.w, h1, l1);
    ((uint2*)hi)[i] = make_uint2(h0, h1);
    ((uint2*)lo)[i] = make_uint2(l0, l1);
}

// mask (fp32, !=0 means masked) -> bitmask words
__global__ __launch_bounds__(256) void maskbits_kernel(const float* __restrict__ mask, int nwords)
{
    int gw = (blockIdx.x * blockDim.x + threadIdx.x) >> 5;
    int lane = threadIdx.x & 31;
    int nw = (gridDim.x * blockDim.x) >> 5;
    for (int w = gw; w < nwords; w += nw) {
        float v = mask[(size_t)w * 32 + lane];
        uint32_t bits = __ballot_sync(0xffffffffu, v != 0.f);
        if (lane == 0) g_mbits[w] = bits;
    }
}

// ---------------------------------------------------------------------------
// bf16-split GEMM via mma.sync: C[8192,512] = A @ W^T + bias
// block 128x128, 512 threads / 16 warps (warp tile 32x32), KC=32,
// cp.async double buffer. QKV=true: z selects wq/wk/wv, bf16 scatter out.
// ---------------------------------------------------------------------------
#define GKC 32
#define GROWB 80
#define GA_BYTES (128 * GROWB)
#define GBUF (4 * GA_BYTES)
#define GEMM_SMEM (2 * GBUF)        // 81920

template <bool QKV>
__global__ __launch_bounds__(512) void mm_kernel(
    const __nv_bfloat16* __restrict__ Ah, const __nv_bfloat16* __restrict__ Al,
    const __nv_bfloat16* __restrict__ Whb, const __nv_bfloat16* __restrict__ Wlb,
    const float* __restrict__ b0a, const float* __restrict__ b1a,
    const float* __restrict__ b2a, float* __restrict__ Cout)
{
    extern __shared__ char smem[];
    const uint32_t sb = smem_u32(smem);
    const int tid = threadIdx.x, lane = tid & 31, wid = tid >> 5;
    const int wm = wid & 3, wn = wid >> 2;          // 4x4 warp grid
    const int bm = blockIdx.y * 128, bn = blockIdx.x * 128;
    const int z = QKV ? blockIdx.z : 0;

    const __nv_bfloat16* Bh = Whb + (size_t)z * WSZ;
    const __nv_bfloat16* Bl = Wlb + (size_t)z * WSZ;
    const float* bias = QKV ? ((z == 0) ? b0a : (z == 1) ? b1a : b2a) : b0a;

    float acc[2][4][4];
#pragma unroll
    for (int i = 0; i < 2; i++)
#pragma unroll
        for (int j = 0; j < 4; j++)
#pragma unroll
            for (int k = 0; k < 4; k++) acc[i][j][k] = 0.f;

    auto load_chunk = [&](int c, int st) {
        uint32_t dst = sb + st * GBUF;
        int k0 = c * GKC;
        const __nv_bfloat16* srcs[4] = {Ah, Al, Bh, Bl};
        int r = tid >> 2, cc = tid & 3;   // 512 threads cover one array per pass
#pragma unroll
        for (int arr = 0; arr < 4; arr++) {
            int rb = (arr < 2) ? bm : bn;
            cpa16(dst + arr * GA_BYTES + r * GROWB + cc * 16,
                  srcs[arr] + (size_t)(rb + r) * DMODEL + k0 + cc * 8);
        }
        CPA_COMMIT();
    };

    load_chunk(0, 0);
    CPA_WAIT0();
    __syncthreads();

    for (int c = 0; c < DMODEL / GKC; ++c) {
        int st = c & 1;
        if (c < DMODEL / GKC - 1) load_chunk(c + 1, st ^ 1);
        uint32_t base = sb + st * GBUF;

        uint32_t ah[2][2][4], al[2][2][4];   // [mf][ks][4]
#pragma unroll
        for (int mf = 0; mf < 2; mf++)
#pragma unroll
            for (int ks = 0; ks < 2; ks++) {
                uint32_t row = wm * 32 + mf * 16 + (lane & 15);
                uint32_t col = ks * 32 + ((lane >> 4) << 4);
                ldsm_x4(ah[mf][ks][0], ah[mf][ks][1], ah[mf][ks][2], ah[mf][ks][3],
                        base + 0 * GA_BYTES + row * GROWB + col);
                ldsm_x4(al[mf][ks][0], al[mf][ks][1], al[mf][ks][2], al[mf][ks][3],
                        base + 1 * GA_BYTES + row * GROWB + col);
            }
#pragma unroll
        for (int nf = 0; nf < 4; nf++) {
            uint32_t row = wn * 32 + nf * 8 + (lane & 7);
            uint32_t col = (lane >> 3) << 4;
            uint32_t bh[4], bl[4];
            ldsm_x4(bh[0], bh[1], bh[2], bh[3], base + 2 * GA_BYTES + row * GROWB + col);
            ldsm_x4(bl[0], bl[1], bl[2], bl[3], base + 3 * GA_BYTES + row * GROWB + col);
#pragma unroll
            for (int ks = 0; ks < 2; ks++)
#pragma unroll
                for (int mf = 0; mf < 2; mf++) {
                    float* C = acc[mf][nf];
                    mma_bf16(C, ah[mf][ks][0], ah[mf][ks][1], ah[mf][ks][2], ah[mf][ks][3],
                             bh[2 * ks], bh[2 * ks + 1]);
                    mma_bf16(C, ah[mf][ks][0], ah[mf][ks][1], ah[mf][ks][2], ah[mf][ks][3],
                             bl[2 * ks], bl[2 * ks + 1]);
                    mma_bf16(C, al[mf][ks][0], al[mf][ks][1], al[mf][ks][2], al[mf][ks][3],
                             bh[2 * ks], bh[2 * ks + 1]);
                }
        }
        if (c < DMODEL / GKC - 1) CPA_WAIT0();
        __syncthreads();
    }

    const int q4 = lane & 3, r4 = lane >> 2;
#pragma unroll
    for (int mf = 0; mf < 2; mf++)
#pragma unroll
        for (int nf = 0; nf < 4; nf++) {
            int col = bn + wn * 32 + nf * 8 + q4 * 2;
            float2 bb = *(const float2*)(bias + col);
#pragma unroll
            for (int hh = 0; hh < 2; hh++) {
                int row = bm + wm * 32 + mf * 16 + r4 + hh * 8;
                float v0 = acc[mf][nf][2 * hh + 0] + bb.x;
                float v1 = acc[mf][nf][2 * hh + 1] + bb.y;
                if (!QKV) {
                    *(float2*)(Cout + (size_t)row * DMODEL + col) = make_float2(v0, v1);
                } else {
                    int b = row >> 10, s = row & 1023, hd = col >> 6, d = col & 63;
                    size_t o = ((size_t)((b * NHEAD + hd) * SLEN + s)) * DKV + d;
                    uint32_t hp, lp;
                    split2(v0, v1, hp, lp);
                    __nv_bfloat16* dh = (z == 0) ? g_qh : (z == 1) ? g_kh : g_vh;
                    __nv_bfloat16* dl = (z == 0) ? g_ql : (z == 1) ? g_kl : g_vl;
                    *(uint32_t*)(dh + o) = hp;
                    *(uint32_t*)(dl + o) = lp;
                }
            }
        }
}

// ---------------------------------------------------------------------------
// Flash attention via mma.sync, bf16 hi/lo split for QK^T and PV.
// Block: 64 q-rows x one (b,h). 4 warps, 16 q-rows each, full 64-col tiles.
// (R3 config; V loads upgraded to ldmatrix.x4.trans.)
// ---------------------------------------------------------------------------
#define AROWB 144
#define AT_BYTES (64 * AROWB)        // 9216
#define ABUF (4 * AT_BYTES)          // Kh,Kl,Vh,Vl = 36864 per stage
#define ATTN_SMEM (2 * ABUF)         // 73728

__global__ __launch_bounds__(128) void attn_kernel()
{
    extern __shared__ char smem[];
    const uint32_t sb = smem_u32(smem);
    const int tid = threadIdx.x, lane = tid & 31, w = tid >> 5;
    const int q4 = lane & 3, r4 = lane >> 2;
    const int qt = blockIdx.x, bh = blockIdx.y;
    const int b = bh >> 3, h = bh & 7;

    const __nv_bfloat16* Qh = g_qh + (size_t)bh * SLEN * DKV + (size_t)qt * 64 * DKV;
    const __nv_bfloat16* Ql = g_ql + (size_t)bh * SLEN * DKV + (size_t)qt * 64 * DKV;
    const __nv_bfloat16* Kh = g_kh + (size_t)bh * SLEN * DKV;
    const __nv_bfloat16* Kl = g_kl + (size_t)bh * SLEN * DKV;
    const __nv_bfloat16* Vh = g_vh + (size_t)bh * SLEN * DKV;
    const __nv_bfloat16* Vl = g_vl + (size_t)bh * SLEN * DKV;

    // ---- stage Q into buffer 1 (arrays 0,1), extract fragments ----
    {
        uint32_t qb = sb + ABUF;
#pragma unroll
        for (int arr = 0; arr < 2; arr++) {
            const __nv_bfloat16* S = arr ? Ql : Qh;
#pragma unroll
            for (int it = 0; it < 4; it++) {
                int idx = tid + it * 128;      // 0..511
                int r = idx >> 3, cc = idx & 7;
                cpa16(qb + arr * AT_BYTES + r * AROWB + cc * 16, S + r * DKV + cc * 8);
            }
        }
        CPA_COMMIT();
        CPA_WAIT0();
        __syncthreads();
    }
    uint32_t qfh[4][4], qfl[4][4];
    {
        uint32_t qb = sb + ABUF;
        uint32_t row = w * 16 + (lane & 15);
#pragma unroll
        for (int ks = 0; ks < 4; ks++) {
            uint32_t col = ks * 32 + ((lane >> 4) << 4);
            ldsm_x4(qfh[ks][0], qfh[ks][1], qfh[ks][2], qfh[ks][3],
                    qb + 0 * AT_BYTES + row * AROWB + col);
            ldsm_x4(qfl[ks][0], qfl[ks][1], qfl[ks][2], qfl[ks][3],
                    qb + 1 * AT_BYTES + row * AROWB + col);
        }
    }

    auto load_tile = [&](int kt, int st) {
        uint32_t dst = sb + st * ABUF;
        const __nv_bfloat16* srcs[4] = {Kh + (size_t)kt * 64 * DKV, Kl + (size_t)kt * 64 * DKV,
                                        Vh + (size_t)kt * 64 * DKV, Vl + (size_t)kt * 64 * DKV};
#pragma unroll
        for (int arr = 0; arr < 4; arr++)
#pragma unroll
            for (int it = 0; it < 4; it++) {
                int idx = tid + it * 128;
                int r = idx >> 3, cc = idx & 7;
                cpa16(dst + arr * AT_BYTES + r * AROWB + cc * 16, srcs[arr] + r * DKV + cc * 8);
            }
        CPA_COMMIT();
    };

    load_tile(0, 0);     // buffer 0 (Q lives in buffer 1; disjoint)
    CPA_WAIT0();
    __syncthreads();     // orders Q-frag reads before tile 1 overwrites buf 1

    float o[8][4];
#pragma unroll
    for (int j = 0; j < 8; j++)
#pragma unroll
        for (int k = 0; k < 4; k++) o[j][k] = 0.f;
    float m0 = -1e30f, m1 = -1e30f, l0 = 0.f, l1 = 0.f;

    const uint32_t* mrow0 = g_mbits + ((size_t)b * SLEN + qt * 64 + w * 16 + r4) * 32;
    const uint32_t* mrow1 = mrow0 + 8 * 32;

    for (int kt = 0; kt < 16; ++kt) {
        int st = kt & 1;
        if (kt < 15) load_tile(kt + 1, st ^ 1);
        uint32_t base = sb + st * ABUF;

        // ---- S = Q @ K^T (fp32 accum, 3-way split) ----
        float s[8][4];
#pragma unroll
        for (int j = 0; j < 8; j++)
#pragma unroll
            for (int k = 0; k < 4; k++) s[j][k] = 0.f;

#pragma unroll
        for (int nf = 0; nf < 8; nf++) {
            uint32_t row = nf * 8 + (lane & 7);
            uint32_t coff = (lane >> 3) << 4;
            uint32_t kh0[4], kh1[4], kl0[4], kl1[4];
            ldsm_x4(kh0[0], kh0[1], kh0[2], kh0[3], base + 0 * AT_BYTES + row * AROWB + coff);
            ldsm_x4(kh1[0], kh1[1], kh1[2], kh1[3], base + 0 * AT_BYTES + row * AROWB + 64 + coff);
            ldsm_x4(kl0[0], kl0[1], kl0[2], kl0[3], base + 1 * AT_BYTES + row * AROWB + coff);
            ldsm_x4(kl1[0], kl1[1], kl1[2], kl1[3], base + 1 * AT_BYTES + row * AROWB + 64 + coff);
#pragma unroll
            for (int ks = 0; ks < 4; ks++) {
                uint32_t* KH = (ks < 2) ? kh0 : kh1;
                uint32_t* KL = (ks < 2) ? kl0 : kl1;
                int kk = (ks & 1) * 2;
                mma_bf16(s[nf], qfh[ks][0], qfh[ks][1], qfh[ks][2], qfh[ks][3], KH[kk], KH[kk + 1]);
                mma_bf16(s[nf], qfh[ks][0], qfh[ks][1], qfh[ks][2], qfh[ks][3], KL[kk], KL[kk + 1]);
                mma_bf16(s[nf], qfl[ks][0], qfl[ks][1], qfl[ks][2], qfl[ks][3], KH[kk], KH[kk + 1]);
            }
        }

        // ---- mask + scale ----
        uint32_t w0a = mrow0[kt * 2], w0b = mrow0[kt * 2 + 1];
        uint32_t w1a = mrow1[kt * 2], w1b = mrow1[kt * 2 + 1];
        float rm0 = -CUDART_INF_F, rm1 = -CUDART_INF_F;
#pragma unroll
        for (int nf = 0; nf < 8; nf++) {
            int c = nf * 8 + q4 * 2;
            uint32_t wr0 = (c < 32) ? w0a : w0b;
            uint32_t wr1 = (c < 32) ? w1a : w1b;
            int sh = c & 31;
            s[nf][0] = ((wr0 >> sh) & 1) ? -CUDART_INF_F : s[nf][0] * 0.125f;
            s[nf][1] = ((wr0 >> (sh + 1)) & 1) ? -CUDART_INF_F : s[nf][1] * 0.125f;
            s[nf][2] = ((wr1 >> sh) & 1) ? -CUDART_INF_F : s[nf][2] * 0.125f;
            s[nf][3] = ((wr1 >> (sh + 1)) & 1) ? -CUDART_INF_F : s[nf][3] * 0.125f;
            rm0 = fmaxf(rm0, fmaxf(s[nf][0], s[nf][1]));
            rm1 = fmaxf(rm1, fmaxf(s[nf][2], s[nf][3]));
        }
        rm0 = fmaxf(rm0, __shfl_xor_sync(0xffffffffu, rm0, 1));
        rm0 = fmaxf(rm0, __shfl_xor_sync(0xffffffffu, rm0, 2));
        rm1 = fmaxf(rm1, __shfl_xor_sync(0xffffffffu, rm1, 1));
        rm1 = fmaxf(rm1, __shfl_xor_sync(0xffffffffu, rm1, 2));

        float mn0 = fmaxf(m0, rm0), mn1 = fmaxf(m1, rm1);
        float sc0 = __expf(m0 - mn0), sc1 = __expf(m1 - mn1);
        float rs0 = 0.f, rs1 = 0.f;
        uint32_t pH01[8], pH23[8], pL01[8], pL23[8];
#pragma unroll
        for (int nf = 0; nf < 8; nf++) {
            float p0 = __expf(s[nf][0] - mn0);
            float p1 = __expf(s[nf][1] - mn0);
            float p2 = __expf(s[nf][2] - mn1);
            float p3 = __expf(s[nf][3] - mn1);
            rs0 += p0 + p1;
            rs1 += p2 + p3;
            split2(p0, p1, pH01[nf], pL01[nf]);
            split2(p2, p3, pH23[nf], pL23[nf]);
        }
        rs0 += __shfl_xor_sync(0xffffffffu, rs0, 1);
        rs0 += __shfl_xor_sync(0xffffffffu, rs0, 2);
        rs1 += __shfl_xor_sync(0xffffffffu, rs1, 1);
        rs1 += __shfl_xor_sync(0xffffffffu, rs1, 2);
        l0 = l0 * sc0 + rs0;
        l1 = l1 * sc1 + rs1;
        m0 = mn0;
        m1 = mn1;
#pragma unroll
        for (int nf = 0; nf < 8; nf++) {
            o[nf][0] *= sc0;
            o[nf][1] *= sc0;
            o[nf][2] *= sc1;
            o[nf][3] *= sc1;
        }

        // ---- O += P @ V  (P frags in registers; V via ldmatrix.x4.trans) ----
#pragma unroll
        for (int ks = 0; ks < 4; ks++) {
            uint32_t a0 = pH01[2 * ks], a1 = pH23[2 * ks];
            uint32_t a2 = pH01[2 * ks + 1], a3 = pH23[2 * ks + 1];
            uint32_t la0 = pL01[2 * ks], la1 = pL23[2 * ks];
            uint32_t la2 = pL01[2 * ks + 1], la3 = pL23[2 * ks + 1];
            uint32_t vaddr = (ks * 16 + (lane & 15)) * AROWB + ((lane >> 4) << 4);
#pragma unroll
            for (int nf2 = 0; nf2 < 4; nf2++) {
                uint32_t vh[4], vl[4];
                ldsm_x4t(vh[0], vh[1], vh[2], vh[3], base + 2 * AT_BYTES + vaddr + nf2 * 32);
                ldsm_x4t(vl[0], vl[1], vl[2], vl[3], base + 3 * AT_BYTES + vaddr + nf2 * 32);
                mma_bf16(o[2 * nf2 + 0], a0, a1, a2, a3, vh[0], vh[1]);
                mma_bf16(o[2 * nf2 + 0], a0, a1, a2, a3, vl[0], vl[1]);
                mma_bf16(o[2 * nf2 + 0], la0, la1, la2, la3, vh[0], vh[1]);
                mma_bf16(o[2 * nf2 + 1], a0, a1, a2, a3, vh[2], vh[3]);
                mma_bf16(o[2 * nf2 + 1], a0, a1, a2, a3, vl[2], vl[3]);
                mma_bf16(o[2 * nf2 + 1], la0, la1, la2, la3, vh[2], vh[3]);
            }
        }

        if (kt < 15) CPA_WAIT0();
        __syncthreads();
    }

    // ---- epilogue: ctx = O / l -> bf16 hi/lo into g_ah/g_al ----
    float il0 = (l0 > 0.f) ? (1.f / l0) : 0.f;
    float il1 = (l1 > 0.f) ? (1.f / l1) : 0.f;
    int row0 = qt * 64 + w * 16 + r4;
#pragma unroll
    for (int nf = 0; nf < 8; nf++) {
        int col = h * 64 + nf * 8 + q4 * 2;
        uint32_t hp, lp;
        split2(o[nf][0] * il0, o[nf][1] * il0, hp, lp);
        *(uint32_t*)(g_ah + (size_t)(b * SLEN + row0) * DMODEL + col) = hp;
        *(uint32_t*)(g_al + (size_t)(b * SLEN + row0) * DMODEL + col) = lp;
        split2(o[nf][2] * il1, o[nf][3] * il1, hp, lp);
        *(uint32_t*)(g_ah + (size_t)(b * SLEN + row0 + 8) * DMODEL + col) = hp;
        *(uint32_t*)(g_al + (size_t)(b * SLEN + row0 + 8) * DMODEL + col) = lp;
    }
}

// ---------------------------------------------------------------------------
extern "C" void kernel_launch(void* const* d_in, const int* in_sizes, int n_in,
                              void* d_out, int out_size)
{
    const float* inputs = (const float*)d_in[0];
    const float* mask   = (const float*)d_in[1];
    const float* wq = (const float*)d_in[2];
    const float* bq = (const float*)d_in[3];
    const float* wk = (const float*)d_in[4];
    const float* bk = (const float*)d_in[5];
    const float* wv = (const float*)d_in[6];
    const float* bv = (const float*)d_in[7];
    const float* wo = (const float*)d_in[8];
    const float* bo = (const float*)d_in[9];
    float* out = (float*)d_out;

    __nv_bfloat16 *ah, *al, *wh, *wl;
    cudaGetSymbolAddress((void**)&ah, g_ah);
    cudaGetSymbolAddress((void**)&al, g_al);
    cudaGetSymbolAddress((void**)&wh, g_wh);
    cudaGetSymbolAddress((void**)&wl, g_wl);

    cvt_kernel<<<(MROWS * DMODEL / 4 + 255) / 256, 256>>>(inputs, ah, al, MROWS * DMODEL / 4);
    cvt_w_kernel<<<dim3((WSZ / 4 + 255) / 256, 1, 4), 256>>>(wq, wk, wv, wo);
    maskbits_kernel<<<256, 256>>>(mask, BATCH * SLEN * (SLEN / 32));

    cudaFuncSetAttribute(mm_kernel<true>, cudaFuncAttributeMaxDynamicSharedMemorySize, GEMM_SMEM);
    cudaFuncSetAttribute(mm_kernel<false>, cudaFuncAttributeMaxDynamicSharedMemorySize, GEMM_SMEM);
    cudaFuncSetAttribute(attn_kernel, cudaFuncAttributeMaxDynamicSharedMemorySize, ATTN_SMEM);

    dim3 gqkv(DMODEL / 128, MROWS / 128, 3);   // (4, 64, 3)
    mm_kernel<true><<<gqkv, 512, GEMM_SMEM>>>(ah, al, wh, wl, bq, bk, bv, nullptr);

    dim3 ga(SLEN / 64, BATCH * NHEAD);         // (16, 64)
    attn_kernel<<<ga, 128, ATTN_SMEM>>>();     // writes ctx hi/lo into g_ah/g_al

    dim3 go(DMODEL / 128, MROWS / 128);        // (4, 64)
    mm_kernel<false><<<go, 512, GEMM_SMEM>>>(ah, al, wh + 3 * WSZ, wl + 3 * WSZ,
                                             bo, nullptr, nullptr, out);
}

// round 6
// speedup vs baseline: 1.1915x; 1.0708x over previous
#include <cuda_runtime.h>
#include <cuda_bf16.h>
#include <math_constants.h>
#include <cstdint>

#define BATCH  8
#define SLEN   1024
#define NHEAD  8
#define DMODEL 512
#define DKV    64
#define MROWS  (BATCH * SLEN)   // 8192
#define WSZ    (DMODEL * DMODEL)

// ---------------------------------------------------------------------------
// Scratch (allocation-free: __device__ globals)
// ---------------------------------------------------------------------------
__device__ __nv_bfloat16 g_ah[MROWS * DMODEL];      // A hi (inputs, later ctx)
__device__ __nv_bfloat16 g_al[MROWS * DMODEL];      // A lo
__device__ __nv_bfloat16 g_wh[4 * WSZ];             // wq|wk|wv|wo hi
__device__ __nv_bfloat16 g_wl[4 * WSZ];             // wq|wk|wv|wo lo
__device__ __nv_bfloat16 g_qh[MROWS * DMODEL], g_ql[MROWS * DMODEL];  // [b,h,s,d]
__device__ __nv_bfloat16 g_kh[MROWS * DMODEL], g_kl[MROWS * DMODEL];
__device__ __nv_bfloat16 g_vh[MROWS * DMODEL], g_vl[MROWS * DMODEL];
__device__ uint32_t g_mbits[BATCH * SLEN * (SLEN / 32)];   // 1MB bitmask

// ---------------------------------------------------------------------------
// Baseline-ISA helpers (sm_80-era: survive the harness's plain sm_103 target)
// ---------------------------------------------------------------------------
__device__ __forceinline__ uint32_t smem_u32(const void* p) {
    uint32_t a;
    asm("{ .reg .u64 t; cvta.to.shared.u64 t, %1; cvt.u32.u64 %0, t; }" : "=r"(a) : "l"(p));
    return a;
}
__device__ __forceinline__ void ldsm_x4(uint32_t& r0, uint32_t& r1, uint32_t& r2,
                                        uint32_t& r3, uint32_t addr) {
    asm volatile("ldmatrix.sync.aligned.m8n8.x4.shared.b16 {%0,%1,%2,%3}, [%4];"
                 : "=r"(r0), "=r"(r1), "=r"(r2), "=r"(r3) : "r"(addr));
}
__device__ __forceinline__ void ldsm_x4t(uint32_t& r0, uint32_t& r1, uint32_t& r2,
                                         uint32_t& r3, uint32_t addr) {
    asm volatile("ldmatrix.sync.aligned.m8n8.x4.trans.shared.b16 {%0,%1,%2,%3}, [%4];"
                 : "=r"(r0), "=r"(r1), "=r"(r2), "=r"(r3) : "r"(addr));
}
__device__ __forceinline__ void mma_bf16(float* c, uint32_t a0, uint32_t a1, uint32_t a2,
                                         uint32_t a3, uint32_t b0, uint32_t b1) {
    asm volatile("mma.sync.aligned.m16n8k16.row.col.f32.bf16.bf16.f32 "
                 "{%0,%1,%2,%3}, {%4,%5,%6,%7}, {%8,%9}, {%0,%1,%2,%3};"
                 : "+f"(c[0]), "+f"(c[1]), "+f"(c[2]), "+f"(c[3])
                 : "r"(a0), "r"(a1), "r"(a2), "r"(a3), "r"(b0), "r"(b1));
}
__device__ __forceinline__ void cpa16(uint32_t s, const void* g) {
    asm volatile("cp.async.cg.shared.global [%0], [%1], 16;" :: "r"(s), "l"(g));
}
#define CPA_COMMIT() asm volatile("cp.async.commit_group;" ::: "memory")
#define CPA_WAIT0()  asm volatile("cp.async.wait_group 0;" ::: "memory")

__device__ __forceinline__ uint32_t pack2h(__nv_bfloat16 lo, __nv_bfloat16 hi) {
    return ((uint32_t)__bfloat16_as_ushort(hi) << 16) | __bfloat16_as_ushort(lo);
}
__device__ __forceinline__ void split2(float x, float y, uint32_t& hp, uint32_t& lp) {
    __nv_bfloat16 hx = __float2bfloat16(x), hy = __float2bfloat16(y);
    hp = pack2h(hx, hy);
    lp = pack2h(__float2bfloat16(x - __bfloat162float(hx)),
                __float2bfloat16(y - __bfloat162float(hy)));
}

// ---------------------------------------------------------------------------
// fp32 -> bf16 hi/lo split (inputs / ctx)
// ---------------------------------------------------------------------------
__global__ __launch_bounds__(256) void cvt_kernel(
    const float* __restrict__ src, __nv_bfloat16* __restrict__ hi,
    __nv_bfloat16* __restrict__ lo, int n4)
{
    int i = blockIdx.x * 256 + threadIdx.x;
    if (i >= n4) return;
    float4 v = ((const float4*)src)[i];
    uint32_t h0, l0, h1, l1;
    split2(v.x, v.y, h0, l0);
    split2(v.z, v.w, h1, l1);
    ((uint2*)hi)[i] = make_uint2(h0, h1);
    ((uint2*)lo)[i] = make_uint2(l0, l1);
}

// All 4 weight matrices in one launch (z selects)
__global__ __launch_bounds__(256) void cvt_w_kernel(
    const float* __restrict__ w0, const float* __restrict__ w1,
    const float* __restrict__ w2, const float* __restrict__ w3)
{
    int z = blockIdx.z;
    const float* src = (z == 0) ? w0 : (z == 1) ? w1 : (z == 2) ? w2 : w3;
    __nv_bfloat16* hi = g_wh + (size_t)z * WSZ;
    __nv_bfloat16* lo = g_wl + (size_t)z * WSZ;
    int i = blockIdx.x * 256 + threadIdx.x;
    if (i >= WSZ / 4) return;
    float4 v = ((const float4*)src)[i];
    uint32_t h0, l0, h1, l1;
    split2(v.x, v.y, h0, l0);
    split2(v.z, v.w, h1, l1);
    ((uint2*)hi)[i] = make_uint2(h0, h1);
    ((uint2*)lo)[i] = make_uint2(l0, l1);
}

// mask (fp32, !=0 means masked) -> bitmask words
__global__ __launch_bounds__(256) void maskbits_kernel(const float* __restrict__ mask, int nwords)
{
    int gw = (blockIdx.x * blockDim.x + threadIdx.x) >> 5;
    int lane = threadIdx.x & 31;
    int nw = (gridDim.x * blockDim.x) >> 5;
    for (int w = gw; w < nwords; w += nw) {
        float v = mask[(size_t)w * 32 + lane];
        uint32_t bits = __ballot_sync(0xffffffffu, v != 0.f);
        if (lane == 0) g_mbits[w] = bits;
    }
}

// ---------------------------------------------------------------------------
// bf16-split GEMM via mma.sync: C[8192,512] = A @ W^T + bias
// block 128x128, 512 threads / 16 warps (warp tile 32x32), KC=32,
// cp.async double buffer. MMAs round-robin across 8 accumulators.
// ---------------------------------------------------------------------------
#define GKC 32
#define GROWB 80
#define GA_BYTES (128 * GROWB)
#define GBUF (4 * GA_BYTES)
#define GEMM_SMEM (2 * GBUF)        // 81920

template <bool QKV>
__global__ __launch_bounds__(512) void mm_kernel(
    const __nv_bfloat16* __restrict__ Ah, const __nv_bfloat16* __restrict__ Al,
    const __nv_bfloat16* __restrict__ Whb, const __nv_bfloat16* __restrict__ Wlb,
    const float* __restrict__ b0a, const float* __restrict__ b1a,
    const float* __restrict__ b2a, float* __restrict__ Cout)
{
    extern __shared__ char smem[];
    const uint32_t sb = smem_u32(smem);
    const int tid = threadIdx.x, lane = tid & 31, wid = tid >> 5;
    const int wm = wid & 3, wn = wid >> 2;          // 4x4 warp grid
    const int bm = blockIdx.y * 128, bn = blockIdx.x * 128;
    const int z = QKV ? blockIdx.z : 0;

    const __nv_bfloat16* Bh = Whb + (size_t)z * WSZ;
    const __nv_bfloat16* Bl = Wlb + (size_t)z * WSZ;
    const float* bias = QKV ? ((z == 0) ? b0a : (z == 1) ? b1a : b2a) : b0a;

    float acc[2][4][4];
#pragma unroll
    for (int i = 0; i < 2; i++)
#pragma unroll
        for (int j = 0; j < 4; j++)
#pragma unroll
            for (int k = 0; k < 4; k++) acc[i][j][k] = 0.f;

    auto load_chunk = [&](int c, int st) {
        uint32_t dst = sb + st * GBUF;
        int k0 = c * GKC;
        const __nv_bfloat16* srcs[4] = {Ah, Al, Bh, Bl};
        int r = tid >> 2, cc = tid & 3;
#pragma unroll
        for (int arr = 0; arr < 4; arr++) {
            int rb = (arr < 2) ? bm : bn;
            cpa16(dst + arr * GA_BYTES + r * GROWB + cc * 16,
                  srcs[arr] + (size_t)(rb + r) * DMODEL + k0 + cc * 8);
        }
        CPA_COMMIT();
    };

    load_chunk(0, 0);
    CPA_WAIT0();
    __syncthreads();

    const int m4 = lane >> 3;            // ldsm matrix id 0..3
    const int half = m4 & 1, sub = m4 >> 1;

    for (int c = 0; c < DMODEL / GKC; ++c) {
        int st = c & 1;
        if (c < DMODEL / GKC - 1) load_chunk(c + 1, st ^ 1);
        uint32_t base = sb + st * GBUF;

        // A fragments (both ks, hi+lo)
        uint32_t ah[2][2][4], al[2][2][4];   // [mf][ks][4]
#pragma unroll
        for (int mf = 0; mf < 2; mf++)
#pragma unroll
            for (int ks = 0; ks < 2; ks++) {
                uint32_t row = wm * 32 + mf * 16 + (lane & 15);
                uint32_t col = ks * 32 + ((lane >> 4) << 4);
                ldsm_x4(ah[mf][ks][0], ah[mf][ks][1], ah[mf][ks][2], ah[mf][ks][3],
                        base + 0 * GA_BYTES + row * GROWB + col);
                ldsm_x4(al[mf][ks][0], al[mf][ks][1], al[mf][ks][2], al[mf][ks][3],
                        base + 1 * GA_BYTES + row * GROWB + col);
            }

        // Per ks: load B pairs for all 4 nf, then round-robin MMAs over 8 accs
#pragma unroll
        for (int ks = 0; ks < 2; ks++) {
            uint32_t bh[4][2], bl[4][2];
#pragma unroll
            for (int g = 0; g < 2; g++) {
                // ldsm matrix m -> (nf = g*2 + m/2, k-half = m&1) at fixed ks
                uint32_t row = wn * 32 + (g * 2 + sub) * 8 + (lane & 7);
                uint32_t ad = base + 2 * GA_BYTES + row * GROWB + ks * 32 + half * 16;
                ldsm_x4(bh[g * 2][0], bh[g * 2][1], bh[g * 2 + 1][0], bh[g * 2 + 1][1], ad);
                ldsm_x4(bl[g * 2][0], bl[g * 2][1], bl[g * 2 + 1][0], bl[g * 2 + 1][1],
                        ad + GA_BYTES);
            }
#pragma unroll
            for (int p = 0; p < 3; p++)
#pragma unroll
                for (int mf = 0; mf < 2; mf++)
#pragma unroll
                    for (int nf = 0; nf < 4; nf++) {
                        const uint32_t* A = (p < 2) ? ah[mf][ks] : al[mf][ks];
                        const uint32_t* B = (p == 1) ? bl[nf] : bh[nf];
                        mma_bf16(acc[mf][nf], A[0], A[1], A[2], A[3], B[0], B[1]);
                    }
        }
        if (c < DMODEL / GKC - 1) CPA_WAIT0();
        __syncthreads();
    }

    const int q4 = lane & 3, r4 = lane >> 2;
#pragma unroll
    for (int mf = 0; mf < 2; mf++)
#pragma unroll
        for (int nf = 0; nf < 4; nf++) {
            int col = bn + wn * 32 + nf * 8 + q4 * 2;
            float2 bb = *(const float2*)(bias + col);
#pragma unroll
            for (int hh = 0; hh < 2; hh++) {
                int row = bm + wm * 32 + mf * 16 + r4 + hh * 8;
                float v0 = acc[mf][nf][2 * hh + 0] + bb.x;
                float v1 = acc[mf][nf][2 * hh + 1] + bb.y;
                if (!QKV) {
                    *(float2*)(Cout + (size_t)row * DMODEL + col) = make_float2(v0, v1);
                } else {
                    int b = row >> 10, s = row & 1023, hd = col >> 6, d = col & 63;
                    size_t o = ((size_t)((b * NHEAD + hd) * SLEN + s)) * DKV + d;
                    uint32_t hp, lp;
                    split2(v0, v1, hp, lp);
                    __nv_bfloat16* dh = (z == 0) ? g_qh : (z == 1) ? g_kh : g_vh;
                    __nv_bfloat16* dl = (z == 0) ? g_ql : (z == 1) ? g_kl : g_vl;
                    *(uint32_t*)(dh + o) = hp;
                    *(uint32_t*)(dl + o) = lp;
                }
            }
        }
}

// ---------------------------------------------------------------------------
// Flash attention via mma.sync, bf16 hi/lo split for QK^T and PV.
// Block: 64 q-rows x one (b,h). 4 warps, 16 q-rows each, full 64-col tiles.
// MMAs round-robin across 8 accumulators (reuse distance 8).
// ---------------------------------------------------------------------------
#define AROWB 144
#define AT_BYTES (64 * AROWB)        // 9216
#define ABUF (4 * AT_BYTES)          // Kh,Kl,Vh,Vl = 36864 per stage
#define ATTN_SMEM (2 * ABUF)         // 73728

__global__ __launch_bounds__(128) void attn_kernel()
{
    extern __shared__ char smem[];
    const uint32_t sb = smem_u32(smem);
    const int tid = threadIdx.x, lane = tid & 31, w = tid >> 5;
    const int q4 = lane & 3, r4 = lane >> 2;
    const int qt = blockIdx.x, bh = blockIdx.y;
    const int b = bh >> 3, h = bh & 7;

    const __nv_bfloat16* Qh = g_qh + (size_t)bh * SLEN * DKV + (size_t)qt * 64 * DKV;
    const __nv_bfloat16* Ql = g_ql + (size_t)bh * SLEN * DKV + (size_t)qt * 64 * DKV;
    const __nv_bfloat16* Kh = g_kh + (size_t)bh * SLEN * DKV;
    const __nv_bfloat16* Kl = g_kl + (size_t)bh * SLEN * DKV;
    const __nv_bfloat16* Vh = g_vh + (size_t)bh * SLEN * DKV;
    const __nv_bfloat16* Vl = g_vl + (size_t)bh * SLEN * DKV;

    // ---- stage Q into buffer 1 (arrays 0,1), extract fragments ----
    {
        uint32_t qb = sb + ABUF;
#pragma unroll
        for (int arr = 0; arr < 2; arr++) {
            const __nv_bfloat16* S = arr ? Ql : Qh;
#pragma unroll
            for (int it = 0; it < 4; it++) {
                int idx = tid + it * 128;      // 0..511
                int r = idx >> 3, cc = idx & 7;
                cpa16(qb + arr * AT_BYTES + r * AROWB + cc * 16, S + r * DKV + cc * 8);
            }
        }
        CPA_COMMIT();
        CPA_WAIT0();
        __syncthreads();
    }
    uint32_t qfh[4][4], qfl[4][4];
    {
        uint32_t qb = sb + ABUF;
        uint32_t row = w * 16 + (lane & 15);
#pragma unroll
        for (int ks = 0; ks < 4; ks++) {
            uint32_t col = ks * 32 + ((lane >> 4) << 4);
            ldsm_x4(qfh[ks][0], qfh[ks][1], qfh[ks][2], qfh[ks][3],
                    qb + 0 * AT_BYTES + row * AROWB + col);
            ldsm_x4(qfl[ks][0], qfl[ks][1], qfl[ks][2], qfl[ks][3],
                    qb + 1 * AT_BYTES + row * AROWB + col);
        }
    }

    auto load_tile = [&](int kt, int st) {
        uint32_t dst = sb + st * ABUF;
        const __nv_bfloat16* srcs[4] = {Kh + (size_t)kt * 64 * DKV, Kl + (size_t)kt * 64 * DKV,
                                        Vh + (size_t)kt * 64 * DKV, Vl + (size_t)kt * 64 * DKV};
#pragma unroll
        for (int arr = 0; arr < 4; arr++)
#pragma unroll
            for (int it = 0; it < 4; it++) {
                int idx = tid + it * 128;
                int r = idx >> 3, cc = idx & 7;
                cpa16(dst + arr * AT_BYTES + r * AROWB + cc * 16, srcs[arr] + r * DKV + cc * 8);
            }
        CPA_COMMIT();
    };

    load_tile(0, 0);     // buffer 0 (Q lives in buffer 1; disjoint)
    CPA_WAIT0();
    __syncthreads();     // orders Q-frag reads before tile 1 overwrites buf 1

    float o[8][4];
#pragma unroll
    for (int j = 0; j < 8; j++)
#pragma unroll
        for (int k = 0; k < 4; k++) o[j][k] = 0.f;
    float m0 = -1e30f, m1 = -1e30f, l0 = 0.f, l1 = 0.f;

    const uint32_t* mrow0 = g_mbits + ((size_t)b * SLEN + qt * 64 + w * 16 + r4) * 32;
    const uint32_t* mrow1 = mrow0 + 8 * 32;

    const int m4 = lane >> 3, half = m4 & 1, sub = m4 >> 1;

    for (int kt = 0; kt < 16; ++kt) {
        int st = kt & 1;
        if (kt < 15) load_tile(kt + 1, st ^ 1);
        uint32_t base = sb + st * ABUF;

        // ---- S = Q @ K^T: per ks load all 8 K-pairs, round-robin 8 accs ----
        float s[8][4];
#pragma unroll
        for (int j = 0; j < 8; j++)
#pragma unroll
            for (int k = 0; k < 4; k++) s[j][k] = 0.f;

#pragma unroll
        for (int ks = 0; ks < 4; ks++) {
            uint32_t kh[8][2], kl[8][2];
#pragma unroll
            for (int g = 0; g < 4; g++) {
                uint32_t row = (g * 2 + sub) * 8 + (lane & 7);
                uint32_t ad = base + row * AROWB + ks * 32 + half * 16;
                ldsm_x4(kh[g * 2][0], kh[g * 2][1], kh[g * 2 + 1][0], kh[g * 2 + 1][1], ad);
                ldsm_x4(kl[g * 2][0], kl[g * 2][1], kl[g * 2 + 1][0], kl[g * 2 + 1][1],
                        ad + AT_BYTES);
            }
#pragma unroll
            for (int p = 0; p < 3; p++)
#pragma unroll
                for (int nf = 0; nf < 8; nf++) {
                    const uint32_t* A = (p < 2) ? qfh[ks] : qfl[ks];
                    const uint32_t* B = (p == 1) ? kl[nf] : kh[nf];
                    mma_bf16(s[nf], A[0], A[1], A[2], A[3], B[0], B[1]);
                }
        }

        // ---- mask + scale ----
        uint32_t w0a = mrow0[kt * 2], w0b = mrow0[kt * 2 + 1];
        uint32_t w1a = mrow1[kt * 2], w1b = mrow1[kt * 2 + 1];
        float rm0 = -CUDART_INF_F, rm1 = -CUDART_INF_F;
#pragma unroll
        for (int nf = 0; nf < 8; nf++) {
            int c = nf * 8 + q4 * 2;
            uint32_t wr0 = (c < 32) ? w0a : w0b;
            uint32_t wr1 = (c < 32) ? w1a : w1b;
            int sh = c & 31;
            s[nf][0] = ((wr0 >> sh) & 1) ? -CUDART_INF_F : s[nf][0] * 0.125f;
            s[nf][1] = ((wr0 >> (sh + 1)) & 1) ? -CUDART_INF_F : s[nf][1] * 0.125f;
            s[nf][2] = ((wr1 >> sh) & 1) ? -CUDART_INF_F : s[nf][2] * 0.125f;
            s[nf][3] = ((wr1 >> (sh + 1)) & 1) ? -CUDART_INF_F : s[nf][3] * 0.125f;
            rm0 = fmaxf(rm0, fmaxf(s[nf][0], s[nf][1]));
            rm1 = fmaxf(rm1, fmaxf(s[nf][2], s[nf][3]));
        }
        rm0 = fmaxf(rm0, __shfl_xor_sync(0xffffffffu, rm0, 1));
        rm0 = fmaxf(rm0, __shfl_xor_sync(0xffffffffu, rm0, 2));
        rm1 = fmaxf(rm1, __shfl_xor_sync(0xffffffffu, rm1, 1));
        rm1 = fmaxf(rm1, __shfl_xor_sync(0xffffffffu, rm1, 2));

        float mn0 = fmaxf(m0, rm0), mn1 = fmaxf(m1, rm1);
        float sc0 = __expf(m0 - mn0), sc1 = __expf(m1 - mn1);
        float rs0 = 0.f, rs1 = 0.f;
        uint32_t pH01[8], pH23[8], pL01[8], pL23[8];
#pragma unroll
        for (int nf = 0; nf < 8; nf++) {
            float p0 = __expf(s[nf][0] - mn0);
            float p1 = __expf(s[nf][1] - mn0);
            float p2 = __expf(s[nf][2] - mn1);
            float p3 = __expf(s[nf][3] - mn1);
            rs0 += p0 + p1;
            rs1 += p2 + p3;
            split2(p0, p1, pH01[nf], pL01[nf]);
            split2(p2, p3, pH23[nf], pL23[nf]);
        }
        rs0 += __shfl_xor_sync(0xffffffffu, rs0, 1);
        rs0 += __shfl_xor_sync(0xffffffffu, rs0, 2);
        rs1 += __shfl_xor_sync(0xffffffffu, rs1, 1);
        rs1 += __shfl_xor_sync(0xffffffffu, rs1, 2);
        l0 = l0 * sc0 + rs0;
        l1 = l1 * sc1 + rs1;
        m0 = mn0;
        m1 = mn1;
#pragma unroll
        for (int nf = 0; nf < 8; nf++) {
            o[nf][0] *= sc0;
            o[nf][1] *= sc0;
            o[nf][2] *= sc1;
            o[nf][3] *= sc1;
        }

        // ---- O += P @ V: per ks hoist all V-pairs, round-robin 8 accs ----
#pragma unroll
        for (int ks = 0; ks < 4; ks++) {
            uint32_t a0 = pH01[2 * ks], a1 = pH23[2 * ks];
            uint32_t a2 = pH01[2 * ks + 1], a3 = pH23[2 * ks + 1];
            uint32_t la0 = pL01[2 * ks], la1 = pL23[2 * ks];
            uint32_t la2 = pL01[2 * ks + 1], la3 = pL23[2 * ks + 1];
            uint32_t vaddr = (ks * 16 + (lane & 15)) * AROWB + ((lane >> 4) << 4);
            uint32_t vh[16], vl[16];
#pragma unroll
            for (int nf2 = 0; nf2 < 4; nf2++) {
                ldsm_x4t(vh[nf2 * 4 + 0], vh[nf2 * 4 + 1], vh[nf2 * 4 + 2], vh[nf2 * 4 + 3],
                         base + 2 * AT_BYTES + vaddr + nf2 * 32);
                ldsm_x4t(vl[nf2 * 4 + 0], vl[nf2 * 4 + 1], vl[nf2 * 4 + 2], vl[nf2 * 4 + 3],
                         base + 3 * AT_BYTES + vaddr + nf2 * 32);
            }
#pragma unroll
            for (int p = 0; p < 3; p++)
#pragma unroll
                for (int j = 0; j < 8; j++) {
                    if (p == 0)      mma_bf16(o[j], a0, a1, a2, a3, vh[2 * j], vh[2 * j + 1]);
                    else if (p == 1) mma_bf16(o[j], a0, a1, a2, a3, vl[2 * j], vl[2 * j + 1]);
                    else             mma_bf16(o[j], la0, la1, la2, la3, vh[2 * j], vh[2 * j + 1]);
                }
        }

        if (kt < 15) CPA_WAIT0();
        __syncthreads();
    }

    // ---- epilogue: ctx = O / l -> bf16 hi/lo into g_ah/g_al ----
    float il0 = (l0 > 0.f) ? (1.f / l0) : 0.f;
    float il1 = (l1 > 0.f) ? (1.f / l1) : 0.f;
    int row0 = qt * 64 + w * 16 + r4;
#pragma unroll
    for (int nf = 0; nf < 8; nf++) {
        int col = h * 64 + nf * 8 + q4 * 2;
        uint32_t hp, lp;
        split2(o[nf][0] * il0, o[nf][1] * il0, hp, lp);
        *(uint32_t*)(g_ah + (size_t)(b * SLEN + row0) * DMODEL + col) = hp;
        *(uint32_t*)(g_al + (size_t)(b * SLEN + row0) * DMODEL + col) = lp;
        split2(o[nf][2] * il1, o[nf][3] * il1, hp, lp);
        *(uint32_t*)(g_ah + (size_t)(b * SLEN + row0 + 8) * DMODEL + col) = hp;
        *(uint32_t*)(g_al + (size_t)(b * SLEN + row0 + 8) * DMODEL + col) = lp;
    }
}

// ---------------------------------------------------------------------------
extern "C" void kernel_launch(void* const* d_in, const int* in_sizes, int n_in,
                              void* d_out, int out_size)
{
    const float* inputs = (const float*)d_in[0];
    const float* mask   = (const float*)d_in[1];
    const float* wq = (const float*)d_in[2];
    const float* bq = (const float*)d_in[3];
    const float* wk = (const float*)d_in[4];
    const float* bk = (const float*)d_in[5];
    const float* wv = (const float*)d_in[6];
    const float* bv = (const float*)d_in[7];
    const float* wo = (const float*)d_in[8];
    const float* bo = (const float*)d_in[9];
    float* out = (float*)d_out;

    __nv_bfloat16 *ah, *al, *wh, *wl;
    cudaGetSymbolAddress((void**)&ah, g_ah);
    cudaGetSymbolAddress((void**)&al, g_al);
    cudaGetSymbolAddress((void**)&wh, g_wh);
    cudaGetSymbolAddress((void**)&wl, g_wl);

    cvt_kernel<<<(MROWS * DMODEL / 4 + 255) / 256, 256>>>(inputs, ah, al, MROWS * DMODEL / 4);
    cvt_w_kernel<<<dim3((WSZ / 4 + 255) / 256, 1, 4), 256>>>(wq, wk, wv, wo);
    maskbits_kernel<<<256, 256>>>(mask, BATCH * SLEN * (SLEN / 32));

    cudaFuncSetAttribute(mm_kernel<true>, cudaFuncAttributeMaxDynamicSharedMemorySize, GEMM_SMEM);
    cudaFuncSetAttribute(mm_kernel<false>, cudaFuncAttributeMaxDynamicSharedMemorySize, GEMM_SMEM);
    cudaFuncSetAttribute(attn_kernel, cudaFuncAttributeMaxDynamicSharedMemorySize, ATTN_SMEM);

    dim3 gqkv(DMODEL / 128, MROWS / 128, 3);   // (4, 64, 3)
    mm_kernel<true><<<gqkv, 512, GEMM_SMEM>>>(ah, al, wh, wl, bq, bk, bv, nullptr);

    dim3 ga(SLEN / 64, BATCH * NHEAD);         // (16, 64)
    attn_kernel<<<ga, 128, ATTN_SMEM>>>();     // writes ctx hi/lo into g_ah/g_al

    dim3 go(DMODEL / 128, MROWS / 128);        // (4, 64)
    mm_kernel<false><<<go, 512, GEMM_SMEM>>>(ah, al, wh + 3 * WSZ, wl + 3 * WSZ,
                                             bo, nullptr, nullptr, out);
}

// round 7
// speedup vs baseline: 1.2562x; 1.0543x over previous
#include <cuda_runtime.h>
#include <cuda_bf16.h>
#include <math_constants.h>
#include <cstdint>

#define BATCH  8
#define SLEN   1024
#define NHEAD  8
#define DMODEL 512
#define DKV    64
#define MROWS  (BATCH * SLEN)   // 8192
#define WSZ    (DMODEL * DMODEL)

// ---------------------------------------------------------------------------
// Scratch (allocation-free: __device__ globals)
// ---------------------------------------------------------------------------
__device__ __nv_bfloat16 g_ah[MROWS * DMODEL];      // A hi (inputs, later ctx)
__device__ __nv_bfloat16 g_al[MROWS * DMODEL];      // A lo
__device__ __nv_bfloat16 g_wh[4 * WSZ];             // wq|wk|wv|wo hi
__device__ __nv_bfloat16 g_wl[4 * WSZ];             // wq|wk|wv|wo lo
__device__ __nv_bfloat16 g_qh[MROWS * DMODEL], g_ql[MROWS * DMODEL];  // [b,h,s,d]
__device__ __nv_bfloat16 g_kh[MROWS * DMODEL], g_kl[MROWS * DMODEL];
__device__ __nv_bfloat16 g_vh[MROWS * DMODEL], g_vl[MROWS * DMODEL];
__device__ uint32_t g_mbits[BATCH * SLEN * (SLEN / 32)];   // 1MB bitmask

// ---------------------------------------------------------------------------
// Baseline-ISA helpers (sm_80-era: survive the harness's plain sm_103 target)
// ---------------------------------------------------------------------------
__device__ __forceinline__ uint32_t smem_u32(const void* p) {
    uint32_t a;
    asm("{ .reg .u64 t; cvta.to.shared.u64 t, %1; cvt.u32.u64 %0, t; }" : "=r"(a) : "l"(p));
    return a;
}
__device__ __forceinline__ void ldsm_x4(uint32_t& r0, uint32_t& r1, uint32_t& r2,
                                        uint32_t& r3, uint32_t addr) {
    asm volatile("ldmatrix.sync.aligned.m8n8.x4.shared.b16 {%0,%1,%2,%3}, [%4];"
                 : "=r"(r0), "=r"(r1), "=r"(r2), "=r"(r3) : "r"(addr));
}
__device__ __forceinline__ void ldsm_x4t(uint32_t& r0, uint32_t& r1, uint32_t& r2,
                                         uint32_t& r3, uint32_t addr) {
    asm volatile("ldmatrix.sync.aligned.m8n8.x4.trans.shared.b16 {%0,%1,%2,%3}, [%4];"
                 : "=r"(r0), "=r"(r1), "=r"(r2), "=r"(r3) : "r"(addr));
}
__device__ __forceinline__ void mma_bf16(float* c, uint32_t a0, uint32_t a1, uint32_t a2,
                                         uint32_t a3, uint32_t b0, uint32_t b1) {
    asm volatile("mma.sync.aligned.m16n8k16.row.col.f32.bf16.bf16.f32 "
                 "{%0,%1,%2,%3}, {%4,%5,%6,%7}, {%8,%9}, {%0,%1,%2,%3};"
                 : "+f"(c[0]), "+f"(c[1]), "+f"(c[2]), "+f"(c[3])
                 : "r"(a0), "r"(a1), "r"(a2), "r"(a3), "r"(b0), "r"(b1));
}
__device__ __forceinline__ void cpa16(uint32_t s, const void* g) {
    asm volatile("cp.async.cg.shared.global [%0], [%1], 16;" :: "r"(s), "l"(g));
}
#define CPA_COMMIT() asm volatile("cp.async.commit_group;" ::: "memory")
#define CPA_WAIT0()  asm volatile("cp.async.wait_group 0;" ::: "memory")

__device__ __forceinline__ uint32_t pack2h(__nv_bfloat16 lo, __nv_bfloat16 hi) {
    return ((uint32_t)__bfloat16_as_ushort(hi) << 16) | __bfloat16_as_ushort(lo);
}
__device__ __forceinline__ void split2(float x, float y, uint32_t& hp, uint32_t& lp) {
    __nv_bfloat16 hx = __float2bfloat16(x), hy = __float2bfloat16(y);
    hp = pack2h(hx, hy);
    lp = pack2h(__float2bfloat16(x - __bfloat162float(hx)),
                __float2bfloat16(y - __bfloat162float(hy)));
}

// ---------------------------------------------------------------------------
// fp32 -> bf16 hi/lo split (inputs / ctx)
// ---------------------------------------------------------------------------
__global__ __launch_bounds__(256) void cvt_kernel(
    const float* __restrict__ src, __nv_bfloat16* __restrict__ hi,
    __nv_bfloat16* __restrict__ lo, int n4)
{
    int i = blockIdx.x * 256 + threadIdx.x;
    if (i >= n4) return;
    float4 v = ((const float4*)src)[i];
    uint32_t h0, l0, h1, l1;
    split2(v.x, v.y, h0, l0);
    split2(v.z, v.w, h1, l1);
    ((uint2*)hi)[i] = make_uint2(h0, h1);
    ((uint2*)lo)[i] = make_uint2(l0, l1);
}

// All 4 weight matrices in one launch (z selects)
__global__ __launch_bounds__(256) void cvt_w_kernel(
    const float* __restrict__ w0, const float* __restrict__ w1,
    const float* __restrict__ w2, const float* __restrict__ w3)
{
    int z = blockIdx.z;
    const float* src = (z == 0) ? w0 : (z == 1) ? w1 : (z == 2) ? w2 : w3;
    __nv_bfloat16* hi = g_wh + (size_t)z * WSZ;
    __nv_bfloat16* lo = g_wl + (size_t)z * WSZ;
    int i = blockIdx.x * 256 + threadIdx.x;
    if (i >= WSZ / 4) return;
    float4 v = ((const float4*)src)[i];
    uint32_t h0, l0, h1, l1;
    split2(v.x, v.y, h0, l0);
    split2(v.z, v.w, h1, l1);
    ((uint2*)hi)[i] = make_uint2(h0, h1);
    ((uint2*)lo)[i] = make_uint2(l0, l1);
}

// mask (fp32, !=0 means masked) -> bitmask words
__global__ __launch_bounds__(256) void maskbits_kernel(const float* __restrict__ mask, int nwords)
{
    int gw = (blockIdx.x * blockDim.x + threadIdx.x) >> 5;
    int lane = threadIdx.x & 31;
    int nw = (gridDim.x * blockDim.x) >> 5;
    for (int w = gw; w < nwords; w += nw) {
        float v = mask[(size_t)w * 32 + lane];
        uint32_t bits = __ballot_sync(0xffffffffu, v != 0.f);
        if (lane == 0) g_mbits[w] = bits;
    }
}

// ---------------------------------------------------------------------------
// bf16-split GEMM via mma.sync: C[8192,512] = A @ W^T + bias
// block 128x256, 512 threads / 16 warps (warp tile 32x64, 4x4 grid), KC=32,
// cp.async double buffer. MMAs round-robin across >=8 accumulators.
// LDSM per HMMA: 128B (was 175B at 32x32 warp tiles).
// ---------------------------------------------------------------------------
#define GKC 32
#define GROWB 80
#define SA_B (128 * GROWB)          // 10240 (one A array)
#define SB_B (256 * GROWB)          // 20480 (one B array)
#define GSTAGE (2 * SA_B + 2 * SB_B)   // 61440
#define GEMM_SMEM (2 * GSTAGE)         // 122880

template <bool QKV>
__global__ __launch_bounds__(512) void mm_kernel(
    const __nv_bfloat16* __restrict__ Ah, const __nv_bfloat16* __restrict__ Al,
    const __nv_bfloat16* __restrict__ Whb, const __nv_bfloat16* __restrict__ Wlb,
    const float* __restrict__ b0a, const float* __restrict__ b1a,
    const float* __restrict__ b2a, float* __restrict__ Cout)
{
    extern __shared__ char smem[];
    const uint32_t sb = smem_u32(smem);
    const int tid = threadIdx.x, lane = tid & 31, wid = tid >> 5;
    const int wm = wid & 3, wn = wid >> 2;          // 4x4 warp grid
    const int bm = blockIdx.y * 128, bn = blockIdx.x * 256;
    const int z = QKV ? blockIdx.z : 0;

    const __nv_bfloat16* Bh = Whb + (size_t)z * WSZ;
    const __nv_bfloat16* Bl = Wlb + (size_t)z * WSZ;
    const float* bias = QKV ? ((z == 0) ? b0a : (z == 1) ? b1a : b2a) : b0a;

    float acc[2][8][4];
#pragma unroll
    for (int i = 0; i < 2; i++)
#pragma unroll
        for (int j = 0; j < 8; j++)
#pragma unroll
            for (int k = 0; k < 4; k++) acc[i][j][k] = 0.f;

    auto load_chunk = [&](int c, int st) {
        uint32_t dst = sb + st * GSTAGE;
        int k0 = c * GKC;
        // A: 128 rows x 4 chunks = 512 -> 1 per thread per array
        {
            int r = tid >> 2, cc = tid & 3;
            cpa16(dst + 0 * SA_B + r * GROWB + cc * 16,
                  Ah + (size_t)(bm + r) * DMODEL + k0 + cc * 8);
            cpa16(dst + 1 * SA_B + r * GROWB + cc * 16,
                  Al + (size_t)(bm + r) * DMODEL + k0 + cc * 8);
        }
        // B: 256 rows x 4 chunks = 1024 -> 2 per thread per array
#pragma unroll
        for (int it = 0; it < 2; it++) {
            int idx = tid + it * 512;
            int r = idx >> 2, cc = idx & 3;
            cpa16(dst + 2 * SA_B + r * GROWB + cc * 16,
                  Bh + (size_t)(bn + r) * DMODEL + k0 + cc * 8);
            cpa16(dst + 2 * SA_B + SB_B + r * GROWB + cc * 16,
                  Bl + (size_t)(bn + r) * DMODEL + k0 + cc * 8);
        }
        CPA_COMMIT();
    };

    load_chunk(0, 0);
    CPA_WAIT0();
    __syncthreads();

    const int m4 = lane >> 3;            // ldsm matrix id 0..3
    const int half = m4 & 1, sub = m4 >> 1;

    for (int c = 0; c < DMODEL / GKC; ++c) {
        int st = c & 1;
        if (c < DMODEL / GKC - 1) load_chunk(c + 1, st ^ 1);
        uint32_t base = sb + st * GSTAGE;

#pragma unroll
        for (int ks = 0; ks < 2; ks++) {
            // A fragments for this ks (hi+lo, both mf)
            uint32_t ah[2][4], al[2][4];
#pragma unroll
            for (int mf = 0; mf < 2; mf++) {
                uint32_t row = wm * 32 + mf * 16 + (lane & 15);
                uint32_t col = ks * 32 + ((lane >> 4) << 4);
                ldsm_x4(ah[mf][0], ah[mf][1], ah[mf][2], ah[mf][3],
                        base + 0 * SA_B + row * GROWB + col);
                ldsm_x4(al[mf][0], al[mf][1], al[mf][2], al[mf][3],
                        base + 1 * SA_B + row * GROWB + col);
            }
            // Two groups of 4 nf each: load B pairs, round-robin 8 accs
#pragma unroll
            for (int hg = 0; hg < 2; hg++) {
                uint32_t bh[4][2], bl[4][2];
#pragma unroll
                for (int g = 0; g < 2; g++) {
                    uint32_t row = wn * 64 + (hg * 4 + g * 2 + sub) * 8 + (lane & 7);
                    uint32_t ad = base + 2 * SA_B + row * GROWB + ks * 32 + half * 16;
                    ldsm_x4(bh[g * 2][0], bh[g * 2][1], bh[g * 2 + 1][0], bh[g * 2 + 1][1], ad);
                    ldsm_x4(bl[g * 2][0], bl[g * 2][1], bl[g * 2 + 1][0], bl[g * 2 + 1][1],
                            ad + SB_B);
                }
#pragma unroll
                for (int p = 0; p < 3; p++)
#pragma unroll
                    for (int mf = 0; mf < 2; mf++)
#pragma unroll
                        for (int nf = 0; nf < 4; nf++) {
                            const uint32_t* A = (p < 2) ? ah[mf] : al[mf];
                            const uint32_t* B = (p == 1) ? bl[nf] : bh[nf];
                            mma_bf16(acc[mf][hg * 4 + nf], A[0], A[1], A[2], A[3], B[0], B[1]);
                        }
            }
        }
        if (c < DMODEL / GKC - 1) CPA_WAIT0();
        __syncthreads();
    }

    const int q4 = lane & 3, r4 = lane >> 2;
#pragma unroll
    for (int mf = 0; mf < 2; mf++)
#pragma unroll
        for (int nf = 0; nf < 8; nf++) {
            int col = bn + wn * 64 + nf * 8 + q4 * 2;
            float2 bb = *(const float2*)(bias + col);
#pragma unroll
            for (int hh = 0; hh < 2; hh++) {
                int row = bm + wm * 32 + mf * 16 + r4 + hh * 8;
                float v0 = acc[mf][nf][2 * hh + 0] + bb.x;
                float v1 = acc[mf][nf][2 * hh + 1] + bb.y;
                if (!QKV) {
                    *(float2*)(Cout + (size_t)row * DMODEL + col) = make_float2(v0, v1);
                } else {
                    int b = row >> 10, s = row & 1023, hd = col >> 6, d = col & 63;
                    size_t o = ((size_t)((b * NHEAD + hd) * SLEN + s)) * DKV + d;
                    uint32_t hp, lp;
                    split2(v0, v1, hp, lp);
                    __nv_bfloat16* dh = (z == 0) ? g_qh : (z == 1) ? g_kh : g_vh;
                    __nv_bfloat16* dl = (z == 0) ? g_ql : (z == 1) ? g_kl : g_vl;
                    *(uint32_t*)(dh + o) = hp;
                    *(uint32_t*)(dl + o) = lp;
                }
            }
        }
}

// ---------------------------------------------------------------------------
// Flash attention via mma.sync, bf16 hi/lo split for QK^T and PV.
// Block: 64 q-rows x one (b,h). 4 warps, 16 q-rows each, full 64-col tiles.
// MMAs round-robin across 8 accumulators (unchanged from R6).
// ---------------------------------------------------------------------------
#define AROWB 144
#define AT_BYTES (64 * AROWB)        // 9216
#define ABUF (4 * AT_BYTES)          // Kh,Kl,Vh,Vl = 36864 per stage
#define ATTN_SMEM (2 * ABUF)         // 73728

__global__ __launch_bounds__(128) void attn_kernel()
{
    extern __shared__ char smem[];
    const uint32_t sb = smem_u32(smem);
    const int tid = threadIdx.x, lane = tid & 31, w = tid >> 5;
    const int q4 = lane & 3, r4 = lane >> 2;
    const int qt = blockIdx.x, bh = blockIdx.y;
    const int b = bh >> 3, h = bh & 7;

    const __nv_bfloat16* Qh = g_qh + (size_t)bh * SLEN * DKV + (size_t)qt * 64 * DKV;
    const __nv_bfloat16* Ql = g_ql + (size_t)bh * SLEN * DKV + (size_t)qt * 64 * DKV;
    const __nv_bfloat16* Kh = g_kh + (size_t)bh * SLEN * DKV;
    const __nv_bfloat16* Kl = g_kl + (size_t)bh * SLEN * DKV;
    const __nv_bfloat16* Vh = g_vh + (size_t)bh * SLEN * DKV;
    const __nv_bfloat16* Vl = g_vl + (size_t)bh * SLEN * DKV;

    // ---- stage Q into buffer 1 (arrays 0,1), extract fragments ----
    {
        uint32_t qb = sb + ABUF;
#pragma unroll
        for (int arr = 0; arr < 2; arr++) {
            const __nv_bfloat16* S = arr ? Ql : Qh;
#pragma unroll
            for (int it = 0; it < 4; it++) {
                int idx = tid + it * 128;      // 0..511
                int r = idx >> 3, cc = idx & 7;
                cpa16(qb + arr * AT_BYTES + r * AROWB + cc * 16, S + r * DKV + cc * 8);
            }
        }
        CPA_COMMIT();
        CPA_WAIT0();
        __syncthreads();
    }
    uint32_t qfh[4][4], qfl[4][4];
    {
        uint32_t qb = sb + ABUF;
        uint32_t row = w * 16 + (lane & 15);
#pragma unroll
        for (int ks = 0; ks < 4; ks++) {
            uint32_t col = ks * 32 + ((lane >> 4) << 4);
            ldsm_x4(qfh[ks][0], qfh[ks][1], qfh[ks][2], qfh[ks][3],
                    qb + 0 * AT_BYTES + row * AROWB + col);
            ldsm_x4(qfl[ks][0], qfl[ks][1], qfl[ks][2], qfl[ks][3],
                    qb + 1 * AT_BYTES + row * AROWB + col);
        }
    }

    auto load_tile = [&](int kt, int st) {
        uint32_t dst = sb + st * ABUF;
        const __nv_bfloat16* srcs[4] = {Kh + (size_t)kt * 64 * DKV, Kl + (size_t)kt * 64 * DKV,
                                        Vh + (size_t)kt * 64 * DKV, Vl + (size_t)kt * 64 * DKV};
#pragma unroll
        for (int arr = 0; arr < 4; arr++)
#pragma unroll
            for (int it = 0; it < 4; it++) {
                int idx = tid + it * 128;
                int r = idx >> 3, cc = idx & 7;
                cpa16(dst + arr * AT_BYTES + r * AROWB + cc * 16, srcs[arr] + r * DKV + cc * 8);
            }
        CPA_COMMIT();
    };

    load_tile(0, 0);     // buffer 0 (Q lives in buffer 1; disjoint)
    CPA_WAIT0();
    __syncthreads();     // orders Q-frag reads before tile 1 overwrites buf 1

    float o[8][4];
#pragma unroll
    for (int j = 0; j < 8; j++)
#pragma unroll
        for (int k = 0; k < 4; k++) o[j][k] = 0.f;
    float m0 = -1e30f, m1 = -1e30f, l0 = 0.f, l1 = 0.f;

    const uint32_t* mrow0 = g_mbits + ((size_t)b * SLEN + qt * 64 + w * 16 + r4) * 32;
    const uint32_t* mrow1 = mrow0 + 8 * 32;

    const int m4 = lane >> 3, half = m4 & 1, sub = m4 >> 1;

    for (int kt = 0; kt < 16; ++kt) {
        int st = kt & 1;
        if (kt < 15) load_tile(kt + 1, st ^ 1);
        uint32_t base = sb + st * ABUF;

        // ---- S = Q @ K^T: per ks load all 8 K-pairs, round-robin 8 accs ----
        float s[8][4];
#pragma unroll
        for (int j = 0; j < 8; j++)
#pragma unroll
            for (int k = 0; k < 4; k++) s[j][k] = 0.f;

#pragma unroll
        for (int ks = 0; ks < 4; ks++) {
            uint32_t kh[8][2], kl[8][2];
#pragma unroll
            for (int g = 0; g < 4; g++) {
                uint32_t row = (g * 2 + sub) * 8 + (lane & 7);
                uint32_t ad = base + row * AROWB + ks * 32 + half * 16;
                ldsm_x4(kh[g * 2][0], kh[g * 2][1], kh[g * 2 + 1][0], kh[g * 2 + 1][1], ad);
                ldsm_x4(kl[g * 2][0], kl[g * 2][1], kl[g * 2 + 1][0], kl[g * 2 + 1][1],
                        ad + AT_BYTES);
            }
#pragma unroll
            for (int p = 0; p < 3; p++)
#pragma unroll
                for (int nf = 0; nf < 8; nf++) {
                    const uint32_t* A = (p < 2) ? qfh[ks] : qfl[ks];
                    const uint32_t* B = (p == 1) ? kl[nf] : kh[nf];
                    mma_bf16(s[nf], A[0], A[1], A[2], A[3], B[0], B[1]);
                }
        }

        // ---- mask + scale ----
        uint32_t w0a = mrow0[kt * 2], w0b = mrow0[kt * 2 + 1];
        uint32_t w1a = mrow1[kt * 2], w1b = mrow1[kt * 2 + 1];
        float rm0 = -CUDART_INF_F, rm1 = -CUDART_INF_F;
#pragma unroll
        for (int nf = 0; nf < 8; nf++) {
            int c = nf * 8 + q4 * 2;
            uint32_t wr0 = (c < 32) ? w0a : w0b;
            uint32_t wr1 = (c < 32) ? w1a : w1b;
            int sh = c & 31;
            s[nf][0] = ((wr0 >> sh) & 1) ? -CUDART_INF_F : s[nf][0] * 0.125f;
            s[nf][1] = ((wr0 >> (sh + 1)) & 1) ? -CUDART_INF_F : s[nf][1] * 0.125f;
            s[nf][2] = ((wr1 >> sh) & 1) ? -CUDART_INF_F : s[nf][2] * 0.125f;
            s[nf][3] = ((wr1 >> (sh + 1)) & 1) ? -CUDART_INF_F : s[nf][3] * 0.125f;
            rm0 = fmaxf(rm0, fmaxf(s[nf][0], s[nf][1]));
            rm1 = fmaxf(rm1, fmaxf(s[nf][2], s[nf][3]));
        }
        rm0 = fmaxf(rm0, __shfl_xor_sync(0xffffffffu, rm0, 1));
        rm0 = fmaxf(rm0, __shfl_xor_sync(0xffffffffu, rm0, 2));
        rm1 = fmaxf(rm1, __shfl_xor_sync(0xffffffffu, rm1, 1));
        rm1 = fmaxf(rm1, __shfl_xor_sync(0xffffffffu, rm1, 2));

        float mn0 = fmaxf(m0, rm0), mn1 = fmaxf(m1, rm1);
        float sc0 = __expf(m0 - mn0), sc1 = __expf(m1 - mn1);
        float rs0 = 0.f, rs1 = 0.f;
        uint32_t pH01[8], pH23[8], pL01[8], pL23[8];
#pragma unroll
        for (int nf = 0; nf < 8; nf++) {
            float p0 = __expf(s[nf][0] - mn0);
            float p1 = __expf(s[nf][1] - mn0);
            float p2 = __expf(s[nf][2] - mn1);
            float p3 = __expf(s[nf][3] - mn1);
            rs0 += p0 + p1;
            rs1 += p2 + p3;
            split2(p0, p1, pH01[nf], pL01[nf]);
            split2(p2, p3, pH23[nf], pL23[nf]);
        }
        rs0 += __shfl_xor_sync(0xffffffffu, rs0, 1);
        rs0 += __shfl_xor_sync(0xffffffffu, rs0, 2);
        rs1 += __shfl_xor_sync(0xffffffffu, rs1, 1);
        rs1 += __shfl_xor_sync(0xffffffffu, rs1, 2);
        l0 = l0 * sc0 + rs0;
        l1 = l1 * sc1 + rs1;
        m0 = mn0;
        m1 = mn1;
#pragma unroll
        for (int nf = 0; nf < 8; nf++) {
            o[nf][0] *= sc0;
            o[nf][1] *= sc0;
            o[nf][2] *= sc1;
            o[nf][3] *= sc1;
        }

        // ---- O += P @ V: per ks hoist all V-pairs, round-robin 8 accs ----
#pragma unroll
        for (int ks = 0; ks < 4; ks++) {
            uint32_t a0 = pH01[2 * ks], a1 = pH23[2 * ks];
            uint32_t a2 = pH01[2 * ks + 1], a3 = pH23[2 * ks + 1];
            uint32_t la0 = pL01[2 * ks], la1 = pL23[2 * ks];
            uint32_t la2 = pL01[2 * ks + 1], la3 = pL23[2 * ks + 1];
            uint32_t vaddr = (ks * 16 + (lane & 15)) * AROWB + ((lane >> 4) << 4);
            uint32_t vh[16], vl[16];
#pragma unroll
            for (int nf2 = 0; nf2 < 4; nf2++) {
                ldsm_x4t(vh[nf2 * 4 + 0], vh[nf2 * 4 + 1], vh[nf2 * 4 + 2], vh[nf2 * 4 + 3],
                         base + 2 * AT_BYTES + vaddr + nf2 * 32);
                ldsm_x4t(vl[nf2 * 4 + 0], vl[nf2 * 4 + 1], vl[nf2 * 4 + 2], vl[nf2 * 4 + 3],
                         base + 3 * AT_BYTES + vaddr + nf2 * 32);
            }
#pragma unroll
            for (int p = 0; p < 3; p++)
#pragma unroll
                for (int j = 0; j < 8; j++) {
                    if (p == 0)      mma_bf16(o[j], a0, a1, a2, a3, vh[2 * j], vh[2 * j + 1]);
                    else if (p == 1) mma_bf16(o[j], a0, a1, a2, a3, vl[2 * j], vl[2 * j + 1]);
                    else             mma_bf16(o[j], la0, la1, la2, la3, vh[2 * j], vh[2 * j + 1]);
                }
        }

        if (kt < 15) CPA_WAIT0();
        __syncthreads();
    }

    // ---- epilogue: ctx = O / l -> bf16 hi/lo into g_ah/g_al ----
    float il0 = (l0 > 0.f) ? (1.f / l0) : 0.f;
    float il1 = (l1 > 0.f) ? (1.f / l1) : 0.f;
    int row0 = qt * 64 + w * 16 + r4;
#pragma unroll
    for (int nf = 0; nf < 8; nf++) {
        int col = h * 64 + nf * 8 + q4 * 2;
        uint32_t hp, lp;
        split2(o[nf][0] * il0, o[nf][1] * il0, hp, lp);
        *(uint32_t*)(g_ah + (size_t)(b * SLEN + row0) * DMODEL + col) = hp;
        *(uint32_t*)(g_al + (size_t)(b * SLEN + row0) * DMODEL + col) = lp;
        split2(o[nf][2] * il1, o[nf][3] * il1, hp, lp);
        *(uint32_t*)(g_ah + (size_t)(b * SLEN + row0 + 8) * DMODEL + col) = hp;
        *(uint32_t*)(g_al + (size_t)(b * SLEN + row0 + 8) * DMODEL + col) = lp;
    }
}

// ---------------------------------------------------------------------------
extern "C" void kernel_launch(void* const* d_in, const int* in_sizes, int n_in,
                              void* d_out, int out_size)
{
    const float* inputs = (const float*)d_in[0];
    const float* mask   = (const float*)d_in[1];
    const float* wq = (const float*)d_in[2];
    const float* bq = (const float*)d_in[3];
    const float* wk = (const float*)d_in[4];
    const float* bk = (const float*)d_in[5];
    const float* wv = (const float*)d_in[6];
    const float* bv = (const float*)d_in[7];
    const float* wo = (const float*)d_in[8];
    const float* bo = (const float*)d_in[9];
    float* out = (float*)d_out;

    __nv_bfloat16 *ah, *al, *wh, *wl;
    cudaGetSymbolAddress((void**)&ah, g_ah);
    cudaGetSymbolAddress((void**)&al, g_al);
    cudaGetSymbolAddress((void**)&wh, g_wh);
    cudaGetSymbolAddress((void**)&wl, g_wl);

    cvt_kernel<<<(MROWS * DMODEL / 4 + 255) / 256, 256>>>(inputs, ah, al, MROWS * DMODEL / 4);
    cvt_w_kernel<<<dim3((WSZ / 4 + 255) / 256, 1, 4), 256>>>(wq, wk, wv, wo);
    maskbits_kernel<<<256, 256>>>(mask, BATCH * SLEN * (SLEN / 32));

    cudaFuncSetAttribute(mm_kernel<true>, cudaFuncAttributeMaxDynamicSharedMemorySize, GEMM_SMEM);
    cudaFuncSetAttribute(mm_kernel<false>, cudaFuncAttributeMaxDynamicSharedMemorySize, GEMM_SMEM);
    cudaFuncSetAttribute(attn_kernel, cudaFuncAttributeMaxDynamicSharedMemorySize, ATTN_SMEM);

    dim3 gqkv(DMODEL / 256, MROWS / 128, 3);   // (2, 64, 3)
    mm_kernel<true><<<gqkv, 512, GEMM_SMEM>>>(ah, al, wh, wl, bq, bk, bv, nullptr);

    dim3 ga(SLEN / 64, BATCH * NHEAD);         // (16, 64)
    attn_kernel<<<ga, 128, ATTN_SMEM>>>();     // writes ctx hi/lo into g_ah/g_al

    dim3 go(DMODEL / 256, MROWS / 128);        // (2, 64)
    mm_kernel<false><<<go, 512, GEMM_SMEM>>>(ah, al, wh + 3 * WSZ, wl + 3 * WSZ,
                                             bo, nullptr, nullptr, out);
}

// round 8
// speedup vs baseline: 1.2652x; 1.0072x over previous
#include <cuda_runtime.h>
#include <cuda_bf16.h>
#include <math_constants.h>
#include <cstdint>

#define BATCH  8
#define SLEN   1024
#define NHEAD  8
#define DMODEL 512
#define DKV    64
#define MROWS  (BATCH * SLEN)   // 8192
#define WSZ    (DMODEL * DMODEL)

// ---------------------------------------------------------------------------
// Scratch (allocation-free: __device__ globals)
// ---------------------------------------------------------------------------
__device__ __nv_bfloat16 g_ah[MROWS * DMODEL];      // A hi (inputs, later ctx)
__device__ __nv_bfloat16 g_al[MROWS * DMODEL];      // A lo
__device__ __nv_bfloat16 g_wh[4 * WSZ];             // wq|wk|wv|wo hi
__device__ __nv_bfloat16 g_wl[4 * WSZ];             // wq|wk|wv|wo lo
__device__ __nv_bfloat16 g_qh[MROWS * DMODEL], g_ql[MROWS * DMODEL];  // [b,h,s,d]
__device__ __nv_bfloat16 g_kh[MROWS * DMODEL], g_kl[MROWS * DMODEL];
__device__ __nv_bfloat16 g_vh[MROWS * DMODEL], g_vl[MROWS * DMODEL];
__device__ uint32_t g_mbits[BATCH * SLEN * (SLEN / 32)];   // 1MB bitmask

// ---------------------------------------------------------------------------
// Baseline-ISA helpers (sm_80-era: survive the harness's plain sm_103 target)
// ---------------------------------------------------------------------------
__device__ __forceinline__ uint32_t smem_u32(const void* p) {
    uint32_t a;
    asm("{ .reg .u64 t; cvta.to.shared.u64 t, %1; cvt.u32.u64 %0, t; }" : "=r"(a) : "l"(p));
    return a;
}
__device__ __forceinline__ void ldsm_x4(uint32_t& r0, uint32_t& r1, uint32_t& r2,
                                        uint32_t& r3, uint32_t addr) {
    asm volatile("ldmatrix.sync.aligned.m8n8.x4.shared.b16 {%0,%1,%2,%3}, [%4];"
                 : "=r"(r0), "=r"(r1), "=r"(r2), "=r"(r3) : "r"(addr));
}
__device__ __forceinline__ void ldsm_x4t(uint32_t& r0, uint32_t& r1, uint32_t& r2,
                                         uint32_t& r3, uint32_t addr) {
    asm volatile("ldmatrix.sync.aligned.m8n8.x4.trans.shared.b16 {%0,%1,%2,%3}, [%4];"
                 : "=r"(r0), "=r"(r1), "=r"(r2), "=r"(r3) : "r"(addr));
}
__device__ __forceinline__ void mma_bf16(float* c, uint32_t a0, uint32_t a1, uint32_t a2,
                                         uint32_t a3, uint32_t b0, uint32_t b1) {
    asm volatile("mma.sync.aligned.m16n8k16.row.col.f32.bf16.bf16.f32 "
                 "{%0,%1,%2,%3}, {%4,%5,%6,%7}, {%8,%9}, {%0,%1,%2,%3};"
                 : "+f"(c[0]), "+f"(c[1]), "+f"(c[2]), "+f"(c[3])
                 : "r"(a0), "r"(a1), "r"(a2), "r"(a3), "r"(b0), "r"(b1));
}
__device__ __forceinline__ void cpa16(uint32_t s, const void* g) {
    asm volatile("cp.async.cg.shared.global [%0], [%1], 16;" :: "r"(s), "l"(g));
}
#define CPA_COMMIT() asm volatile("cp.async.commit_group;" ::: "memory")
#define CPA_WAIT0()  asm volatile("cp.async.wait_group 0;" ::: "memory")

__device__ __forceinline__ uint32_t pack2h(__nv_bfloat16 lo, __nv_bfloat16 hi) {
    return ((uint32_t)__bfloat16_as_ushort(hi) << 16) | __bfloat16_as_ushort(lo);
}
__device__ __forceinline__ void split2(float x, float y, uint32_t& hp, uint32_t& lp) {
    __nv_bfloat16 hx = __float2bfloat16(x), hy = __float2bfloat16(y);
    hp = pack2h(hx, hy);
    lp = pack2h(__float2bfloat16(x - __bfloat162float(hx)),
                __float2bfloat16(y - __bfloat162float(hy)));
}

// ---------------------------------------------------------------------------
// fp32 -> bf16 hi/lo split (inputs / ctx)
// ---------------------------------------------------------------------------
__global__ __launch_bounds__(256) void cvt_kernel(
    const float* __restrict__ src, __nv_bfloat16* __restrict__ hi,
    __nv_bfloat16* __restrict__ lo, int n4)
{
    int i = blockIdx.x * 256 + threadIdx.x;
    if (i >= n4) return;
    float4 v = ((const float4*)src)[i];
    uint32_t h0, l0, h1, l1;
    split2(v.x, v.y, h0, l0);
    split2(v.z, v.w, h1, l1);
    ((uint2*)hi)[i] = make_uint2(h0, h1);
    ((uint2*)lo)[i] = make_uint2(l0, l1);
}

// All 4 weight matrices in one launch (z selects)
__global__ __launch_bounds__(256) void cvt_w_kernel(
    const float* __restrict__ w0, const float* __restrict__ w1,
    const float* __restrict__ w2, const float* __restrict__ w3)
{
    int z = blockIdx.z;
    const float* src = (z == 0) ? w0 : (z == 1) ? w1 : (z == 2) ? w2 : w3;
    __nv_bfloat16* hi = g_wh + (size_t)z * WSZ;
    __nv_bfloat16* lo = g_wl + (size_t)z * WSZ;
    int i = blockIdx.x * 256 + threadIdx.x;
    if (i >= WSZ / 4) return;
    float4 v = ((const float4*)src)[i];
    uint32_t h0, l0, h1, l1;
    split2(v.x, v.y, h0, l0);
    split2(v.z, v.w, h1, l1);
    ((uint2*)hi)[i] = make_uint2(h0, h1);
    ((uint2*)lo)[i] = make_uint2(l0, l1);
}

// mask (fp32, !=0 means masked) -> bitmask words
__global__ __launch_bounds__(256) void maskbits_kernel(const float* __restrict__ mask, int nwords)
{
    int gw = (blockIdx.x * blockDim.x + threadIdx.x) >> 5;
    int lane = threadIdx.x & 31;
    int nw = (gridDim.x * blockDim.x) >> 5;
    for (int w = gw; w < nwords; w += nw) {
        float v = mask[(size_t)w * 32 + lane];
        uint32_t bits = __ballot_sync(0xffffffffu, v != 0.f);
        if (lane == 0) g_mbits[w] = bits;
    }
}

// ---------------------------------------------------------------------------
// bf16-split GEMM via mma.sync: C[8192,512] = A @ W^T + bias
// block 128x128, 256 threads / 8 warps (warp tile 32x64, 4x2 grid), KC=32,
// cp.async double buffer. TWO independent blocks co-resident per SM so one
// block's MMA phase covers the other's ldsm/barrier phase.
// ---------------------------------------------------------------------------
#define GKC 32
#define GROWB 80
#define SAR_B (128 * GROWB)            // 10240 (one array: 128 rows)
#define GSTAGE (4 * SAR_B)             // Ah,Al,Bh,Bl = 40960 per stage
#define GEMM_SMEM (2 * GSTAGE)         // 81920 -> 2 blocks/SM

template <bool QKV>
__global__ __launch_bounds__(256, 2) void mm_kernel(
    const __nv_bfloat16* __restrict__ Ah, const __nv_bfloat16* __restrict__ Al,
    const __nv_bfloat16* __restrict__ Whb, const __nv_bfloat16* __restrict__ Wlb,
    const float* __restrict__ b0a, const float* __restrict__ b1a,
    const float* __restrict__ b2a, float* __restrict__ Cout)
{
    extern __shared__ char smem[];
    const uint32_t sb = smem_u32(smem);
    const int tid = threadIdx.x, lane = tid & 31, wid = tid >> 5;
    const int wm = wid & 3, wn = wid >> 2;          // 4x2 warp grid
    const int bm = blockIdx.y * 128, bn = blockIdx.x * 128;
    const int z = QKV ? blockIdx.z : 0;

    const __nv_bfloat16* Bh = Whb + (size_t)z * WSZ;
    const __nv_bfloat16* Bl = Wlb + (size_t)z * WSZ;
    const float* bias = QKV ? ((z == 0) ? b0a : (z == 1) ? b1a : b2a) : b0a;

    float acc[2][8][4];
#pragma unroll
    for (int i = 0; i < 2; i++)
#pragma unroll
        for (int j = 0; j < 8; j++)
#pragma unroll
            for (int k = 0; k < 4; k++) acc[i][j][k] = 0.f;

    auto load_chunk = [&](int c, int st) {
        uint32_t dst = sb + st * GSTAGE;
        int k0 = c * GKC;
        const __nv_bfloat16* srcs[4] = {Ah, Al, Bh, Bl};
#pragma unroll
        for (int arr = 0; arr < 4; arr++) {
            int rb = (arr < 2) ? bm : bn;
#pragma unroll
            for (int it = 0; it < 2; it++) {
                int idx = tid + it * 256;       // 0..511
                int r = idx >> 2, cc = idx & 3;
                cpa16(dst + arr * SAR_B + r * GROWB + cc * 16,
                      srcs[arr] + (size_t)(rb + r) * DMODEL + k0 + cc * 8);
            }
        }
        CPA_COMMIT();
    };

    load_chunk(0, 0);
    CPA_WAIT0();
    __syncthreads();

    const int m4 = lane >> 3;            // ldsm matrix id 0..3
    const int half = m4 & 1, sub = m4 >> 1;

    for (int c = 0; c < DMODEL / GKC; ++c) {
        int st = c & 1;
        if (c < DMODEL / GKC - 1) load_chunk(c + 1, st ^ 1);
        uint32_t base = sb + st * GSTAGE;

#pragma unroll
        for (int ks = 0; ks < 2; ks++) {
            // A fragments for this ks (hi+lo, both mf)
            uint32_t ah[2][4], al[2][4];
#pragma unroll
            for (int mf = 0; mf < 2; mf++) {
                uint32_t row = wm * 32 + mf * 16 + (lane & 15);
                uint32_t col = ks * 32 + ((lane >> 4) << 4);
                ldsm_x4(ah[mf][0], ah[mf][1], ah[mf][2], ah[mf][3],
                        base + 0 * SAR_B + row * GROWB + col);
                ldsm_x4(al[mf][0], al[mf][1], al[mf][2], al[mf][3],
                        base + 1 * SAR_B + row * GROWB + col);
            }
            // Two groups of 4 nf: load B pairs, round-robin 8 accumulators
#pragma unroll
            for (int hg = 0; hg < 2; hg++) {
                uint32_t bh[4][2], bl[4][2];
#pragma unroll
                for (int g = 0; g < 2; g++) {
                    uint32_t row = wn * 64 + (hg * 4 + g * 2 + sub) * 8 + (lane & 7);
                    uint32_t ad = base + 2 * SAR_B + row * GROWB + ks * 32 + half * 16;
                    ldsm_x4(bh[g * 2][0], bh[g * 2][1], bh[g * 2 + 1][0], bh[g * 2 + 1][1], ad);
                    ldsm_x4(bl[g * 2][0], bl[g * 2][1], bl[g * 2 + 1][0], bl[g * 2 + 1][1],
                            ad + SAR_B);
                }
#pragma unroll
                for (int p = 0; p < 3; p++)
#pragma unroll
                    for (int mf = 0; mf < 2; mf++)
#pragma unroll
                        for (int nf = 0; nf < 4; nf++) {
                            const uint32_t* A = (p < 2) ? ah[mf] : al[mf];
                            const uint32_t* B = (p == 1) ? bl[nf] : bh[nf];
                            mma_bf16(acc[mf][hg * 4 + nf], A[0], A[1], A[2], A[3], B[0], B[1]);
                        }
            }
        }
        if (c < DMODEL / GKC - 1) CPA_WAIT0();
        __syncthreads();
    }

    const int q4 = lane & 3, r4 = lane >> 2;
#pragma unroll
    for (int mf = 0; mf < 2; mf++)
#pragma unroll
        for (int nf = 0; nf < 8; nf++) {
            int col = bn + wn * 64 + nf * 8 + q4 * 2;
            float2 bb = *(const float2*)(bias + col);
#pragma unroll
            for (int hh = 0; hh < 2; hh++) {
                int row = bm + wm * 32 + mf * 16 + r4 + hh * 8;
                float v0 = acc[mf][nf][2 * hh + 0] + bb.x;
                float v1 = acc[mf][nf][2 * hh + 1] + bb.y;
                if (!QKV) {
                    *(float2*)(Cout + (size_t)row * DMODEL + col) = make_float2(v0, v1);
                } else {
                    int b = row >> 10, s = row & 1023, hd = col >> 6, d = col & 63;
                    size_t o = ((size_t)((b * NHEAD + hd) * SLEN + s)) * DKV + d;
                    uint32_t hp, lp;
                    split2(v0, v1, hp, lp);
                    __nv_bfloat16* dh = (z == 0) ? g_qh : (z == 1) ? g_kh : g_vh;
                    __nv_bfloat16* dl = (z == 0) ? g_ql : (z == 1) ? g_kl : g_vl;
                    *(uint32_t*)(dh + o) = hp;
                    *(uint32_t*)(dl + o) = lp;
                }
            }
        }
}

// ---------------------------------------------------------------------------
// Flash attention via mma.sync, bf16 hi/lo split for QK^T and PV.
// Block: 64 q-rows x one (b,h). 4 warps, 16 q-rows each, full 64-col tiles.
// (Unchanged from R7 for clean attribution of the mm change.)
// ---------------------------------------------------------------------------
#define AROWB 144
#define AT_BYTES (64 * AROWB)        // 9216
#define ABUF (4 * AT_BYTES)          // Kh,Kl,Vh,Vl = 36864 per stage
#define ATTN_SMEM (2 * ABUF)         // 73728

__global__ __launch_bounds__(128) void attn_kernel()
{
    extern __shared__ char smem[];
    const uint32_t sb = smem_u32(smem);
    const int tid = threadIdx.x, lane = tid & 31, w = tid >> 5;
    const int q4 = lane & 3, r4 = lane >> 2;
    const int qt = blockIdx.x, bh = blockIdx.y;
    const int b = bh >> 3, h = bh & 7;

    const __nv_bfloat16* Qh = g_qh + (size_t)bh * SLEN * DKV + (size_t)qt * 64 * DKV;
    const __nv_bfloat16* Ql = g_ql + (size_t)bh * SLEN * DKV + (size_t)qt * 64 * DKV;
    const __nv_bfloat16* Kh = g_kh + (size_t)bh * SLEN * DKV;
    const __nv_bfloat16* Kl = g_kl + (size_t)bh * SLEN * DKV;
    const __nv_bfloat16* Vh = g_vh + (size_t)bh * SLEN * DKV;
    const __nv_bfloat16* Vl = g_vl + (size_t)bh * SLEN * DKV;

    // ---- stage Q into buffer 1 (arrays 0,1), extract fragments ----
    {
        uint32_t qb = sb + ABUF;
#pragma unroll
        for (int arr = 0; arr < 2; arr++) {
            const __nv_bfloat16* S = arr ? Ql : Qh;
#pragma unroll
            for (int it = 0; it < 4; it++) {
                int idx = tid + it * 128;      // 0..511
                int r = idx >> 3, cc = idx & 7;
                cpa16(qb + arr * AT_BYTES + r * AROWB + cc * 16, S + r * DKV + cc * 8);
            }
        }
        CPA_COMMIT();
        CPA_WAIT0();
        __syncthreads();
    }
    uint32_t qfh[4][4], qfl[4][4];
    {
        uint32_t qb = sb + ABUF;
        uint32_t row = w * 16 + (lane & 15);
#pragma unroll
        for (int ks = 0; ks < 4; ks++) {
            uint32_t col = ks * 32 + ((lane >> 4) << 4);
            ldsm_x4(qfh[ks][0], qfh[ks][1], qfh[ks][2], qfh[ks][3],
                    qb + 0 * AT_BYTES + row * AROWB + col);
            ldsm_x4(qfl[ks][0], qfl[ks][1], qfl[ks][2], qfl[ks][3],
                    qb + 1 * AT_BYTES + row * AROWB + col);
        }
    }

    auto load_tile = [&](int kt, int st) {
        uint32_t dst = sb + st * ABUF;
        const __nv_bfloat16* srcs[4] = {Kh + (size_t)kt * 64 * DKV, Kl + (size_t)kt * 64 * DKV,
                                        Vh + (size_t)kt * 64 * DKV, Vl + (size_t)kt * 64 * DKV};
#pragma unroll
        for (int arr = 0; arr < 4; arr++)
#pragma unroll
            for (int it = 0; it < 4; it++) {
                int idx = tid + it * 128;
                int r = idx >> 3, cc = idx & 7;
                cpa16(dst + arr * AT_BYTES + r * AROWB + cc * 16, srcs[arr] + r * DKV + cc * 8);
            }
        CPA_COMMIT();
    };

    load_tile(0, 0);     // buffer 0 (Q lives in buffer 1; disjoint)
    CPA_WAIT0();
    __syncthreads();     // orders Q-frag reads before tile 1 overwrites buf 1

    float o[8][4];
#pragma unroll
    for (int j = 0; j < 8; j++)
#pragma unroll
        for (int k = 0; k < 4; k++) o[j][k] = 0.f;
    float m0 = -1e30f, m1 = -1e30f, l0 = 0.f, l1 = 0.f;

    const uint32_t* mrow0 = g_mbits + ((size_t)b * SLEN + qt * 64 + w * 16 + r4) * 32;
    const uint32_t* mrow1 = mrow0 + 8 * 32;

    const int m4 = lane >> 3, half = m4 & 1, sub = m4 >> 1;

    for (int kt = 0; kt < 16; ++kt) {
        int st = kt & 1;
        if (kt < 15) load_tile(kt + 1, st ^ 1);
        uint32_t base = sb + st * ABUF;

        // ---- S = Q @ K^T: per ks load all 8 K-pairs, round-robin 8 accs ----
        float s[8][4];
#pragma unroll
        for (int j = 0; j < 8; j++)
#pragma unroll
            for (int k = 0; k < 4; k++) s[j][k] = 0.f;

#pragma unroll
        for (int ks = 0; ks < 4; ks++) {
            uint32_t kh[8][2], kl[8][2];
#pragma unroll
            for (int g = 0; g < 4; g++) {
                uint32_t row = (g * 2 + sub) * 8 + (lane & 7);
                uint32_t ad = base + row * AROWB + ks * 32 + half * 16;
                ldsm_x4(kh[g * 2][0], kh[g * 2][1], kh[g * 2 + 1][0], kh[g * 2 + 1][1], ad);
                ldsm_x4(kl[g * 2][0], kl[g * 2][1], kl[g * 2 + 1][0], kl[g * 2 + 1][1],
                        ad + AT_BYTES);
            }
#pragma unroll
            for (int p = 0; p < 3; p++)
#pragma unroll
                for (int nf = 0; nf < 8; nf++) {
                    const uint32_t* A = (p < 2) ? qfh[ks] : qfl[ks];
                    const uint32_t* B = (p == 1) ? kl[nf] : kh[nf];
                    mma_bf16(s[nf], A[0], A[1], A[2], A[3], B[0], B[1]);
                }
        }

        // ---- mask + scale ----
        uint32_t w0a = mrow0[kt * 2], w0b = mrow0[kt * 2 + 1];
        uint32_t w1a = mrow1[kt * 2], w1b = mrow1[kt * 2 + 1];
        float rm0 = -CUDART_INF_F, rm1 = -CUDART_INF_F;
#pragma unroll
        for (int nf = 0; nf < 8; nf++) {
            int c = nf * 8 + q4 * 2;
            uint32_t wr0 = (c < 32) ? w0a : w0b;
            uint32_t wr1 = (c < 32) ? w1a : w1b;
            int sh = c & 31;
            s[nf][0] = ((wr0 >> sh) & 1) ? -CUDART_INF_F : s[nf][0] * 0.125f;
            s[nf][1] = ((wr0 >> (sh + 1)) & 1) ? -CUDART_INF_F : s[nf][1] * 0.125f;
            s[nf][2] = ((wr1 >> sh) & 1) ? -CUDART_INF_F : s[nf][2] * 0.125f;
            s[nf][3] = ((wr1 >> (sh + 1)) & 1) ? -CUDART_INF_F : s[nf][3] * 0.125f;
            rm0 = fmaxf(rm0, fmaxf(s[nf][0], s[nf][1]));
            rm1 = fmaxf(rm1, fmaxf(s[nf][2], s[nf][3]));
        }
        rm0 = fmaxf(rm0, __shfl_xor_sync(0xffffffffu, rm0, 1));
        rm0 = fmaxf(rm0, __shfl_xor_sync(0xffffffffu, rm0, 2));
        rm1 = fmaxf(rm1, __shfl_xor_sync(0xffffffffu, rm1, 1));
        rm1 = fmaxf(rm1, __shfl_xor_sync(0xffffffffu, rm1, 2));

        float mn0 = fmaxf(m0, rm0), mn1 = fmaxf(m1, rm1);
        float sc0 = __expf(m0 - mn0), sc1 = __expf(m1 - mn1);
        float rs0 = 0.f, rs1 = 0.f;
        uint32_t pH01[8], pH23[8], pL01[8], pL23[8];
#pragma unroll
        for (int nf = 0; nf < 8; nf++) {
            float p0 = __expf(s[nf][0] - mn0);
            float p1 = __expf(s[nf][1] - mn0);
            float p2 = __expf(s[nf][2] - mn1);
            float p3 = __expf(s[nf][3] - mn1);
            rs0 += p0 + p1;
            rs1 += p2 + p3;
            split2(p0, p1, pH01[nf], pL01[nf]);
            split2(p2, p3, pH23[nf], pL23[nf]);
        }
        rs0 += __shfl_xor_sync(0xffffffffu, rs0, 1);
        rs0 += __shfl_xor_sync(0xffffffffu, rs0, 2);
        rs1 += __shfl_xor_sync(0xffffffffu, rs1, 1);
        rs1 += __shfl_xor_sync(0xffffffffu, rs1, 2);
        l0 = l0 * sc0 + rs0;
        l1 = l1 * sc1 + rs1;
        m0 = mn0;
        m1 = mn1;
#pragma unroll
        for (int nf = 0; nf < 8; nf++) {
            o[nf][0] *= sc0;
            o[nf][1] *= sc0;
            o[nf][2] *= sc1;
            o[nf][3] *= sc1;
        }

        // ---- O += P @ V: per ks hoist all V-pairs, round-robin 8 accs ----
#pragma unroll
        for (int ks = 0; ks < 4; ks++) {
            uint32_t a0 = pH01[2 * ks], a1 = pH23[2 * ks];
            uint32_t a2 = pH01[2 * ks + 1], a3 = pH23[2 * ks + 1];
            uint32_t la0 = pL01[2 * ks], la1 = pL23[2 * ks];
            uint32_t la2 = pL01[2 * ks + 1], la3 = pL23[2 * ks + 1];
            uint32_t vaddr = (ks * 16 + (lane & 15)) * AROWB + ((lane >> 4) << 4);
            uint32_t vh[16], vl[16];
#pragma unroll
            for (int nf2 = 0; nf2 < 4; nf2++) {
                ldsm_x4t(vh[nf2 * 4 + 0], vh[nf2 * 4 + 1], vh[nf2 * 4 + 2], vh[nf2 * 4 + 3],
                         base + 2 * AT_BYTES + vaddr + nf2 * 32);
                ldsm_x4t(vl[nf2 * 4 + 0], vl[nf2 * 4 + 1], vl[nf2 * 4 + 2], vl[nf2 * 4 + 3],
                         base + 3 * AT_BYTES + vaddr + nf2 * 32);
            }
#pragma unroll
            for (int p = 0; p < 3; p++)
#pragma unroll
                for (int j = 0; j < 8; j++) {
                    if (p == 0)      mma_bf16(o[j], a0, a1, a2, a3, vh[2 * j], vh[2 * j + 1]);
                    else if (p == 1) mma_bf16(o[j], a0, a1, a2, a3, vl[2 * j], vl[2 * j + 1]);
                    else             mma_bf16(o[j], la0, la1, la2, la3, vh[2 * j], vh[2 * j + 1]);
                }
        }

        if (kt < 15) CPA_WAIT0();
        __syncthreads();
    }

    // ---- epilogue: ctx = O / l -> bf16 hi/lo into g_ah/g_al ----
    float il0 = (l0 > 0.f) ? (1.f / l0) : 0.f;
    float il1 = (l1 > 0.f) ? (1.f / l1) : 0.f;
    int row0 = qt * 64 + w * 16 + r4;
#pragma unroll
    for (int nf = 0; nf < 8; nf++) {
        int col = h * 64 + nf * 8 + q4 * 2;
        uint32_t hp, lp;
        split2(o[nf][0] * il0, o[nf][1] * il0, hp, lp);
        *(uint32_t*)(g_ah + (size_t)(b * SLEN + row0) * DMODEL + col) = hp;
        *(uint32_t*)(g_al + (size_t)(b * SLEN + row0) * DMODEL + col) = lp;
        split2(o[nf][2] * il1, o[nf][3] * il1, hp, lp);
        *(uint32_t*)(g_ah + (size_t)(b * SLEN + row0 + 8) * DMODEL + col) = hp;
        *(uint32_t*)(g_al + (size_t)(b * SLEN + row0 + 8) * DMODEL + col) = lp;
    }
}

// ---------------------------------------------------------------------------
extern "C" void kernel_launch(void* const* d_in, const int* in_sizes, int n_in,
                              void* d_out, int out_size)
{
    const float* inputs = (const float*)d_in[0];
    const float* mask   = (const float*)d_in[1];
    const float* wq = (const float*)d_in[2];
    const float* bq = (const float*)d_in[3];
    const float* wk = (const float*)d_in[4];
    const float* bk = (const float*)d_in[5];
    const float* wv = (const float*)d_in[6];
    const float* bv = (const float*)d_in[7];
    const float* wo = (const float*)d_in[8];
    const float* bo = (const float*)d_in[9];
    float* out = (float*)d_out;

    __nv_bfloat16 *ah, *al, *wh, *wl;
    cudaGetSymbolAddress((void**)&ah, g_ah);
    cudaGetSymbolAddress((void**)&al, g_al);
    cudaGetSymbolAddress((void**)&wh, g_wh);
    cudaGetSymbolAddress((void**)&wl, g_wl);

    cvt_kernel<<<(MROWS * DMODEL / 4 + 255) / 256, 256>>>(inputs, ah, al, MROWS * DMODEL / 4);
    cvt_w_kernel<<<dim3((WSZ / 4 + 255) / 256, 1, 4), 256>>>(wq, wk, wv, wo);
    maskbits_kernel<<<256, 256>>>(mask, BATCH * SLEN * (SLEN / 32));

    cudaFuncSetAttribute(mm_kernel<true>, cudaFuncAttributeMaxDynamicSharedMemorySize, GEMM_SMEM);
    cudaFuncSetAttribute(mm_kernel<false>, cudaFuncAttributeMaxDynamicSharedMemorySize, GEMM_SMEM);
    cudaFuncSetAttribute(attn_kernel, cudaFuncAttributeMaxDynamicSharedMemorySize, ATTN_SMEM);

    dim3 gqkv(DMODEL / 128, MROWS / 128, 3);   // (4, 64, 3)
    mm_kernel<true><<<gqkv, 256, GEMM_SMEM>>>(ah, al, wh, wl, bq, bk, bv, nullptr);

    dim3 ga(SLEN / 64, BATCH * NHEAD);         // (16, 64)
    attn_kernel<<<ga, 128, ATTN_SMEM>>>();     // writes ctx hi/lo into g_ah/g_al

    dim3 go(DMODEL / 128, MROWS / 128);        // (4, 64)
    mm_kernel<false><<<go, 256, GEMM_SMEM>>>(ah, al, wh + 3 * WSZ, wl + 3 * WSZ,
                                             bo, nullptr, nullptr, out);
}

// round 9
// speedup vs baseline: 1.4394x; 1.1376x over previous
#include <cuda_runtime.h>
#include <cuda_bf16.h>
#include <cuda_fp16.h>
#include <math_constants.h>
#include <cstdint>

#define BATCH  8
#define SLEN   1024
#define NHEAD  8
#define DMODEL 512
#define DKV    64
#define MROWS  (BATCH * SLEN)   // 8192
#define WSZ    (DMODEL * DMODEL)

// ---------------------------------------------------------------------------
// Scratch (allocation-free: __device__ globals)
// ---------------------------------------------------------------------------
__device__ __half g_ah[MROWS * DMODEL];             // A hi fp16 (inputs, later ctx)
__device__ __half g_al[MROWS * DMODEL];             // A lo fp16
__device__ __half g_wh[4 * WSZ];                    // wq|wk|wv|wo hi fp16 (lo dropped)
__device__ __nv_bfloat16 g_qh[MROWS * DMODEL], g_ql[MROWS * DMODEL];  // [b,h,s,d]
__device__ __nv_bfloat16 g_kh[MROWS * DMODEL], g_kl[MROWS * DMODEL];
__device__ __nv_bfloat16 g_vh[MROWS * DMODEL], g_vl[MROWS * DMODEL];
__device__ uint32_t g_mbits[BATCH * SLEN * (SLEN / 32)];   // 1MB bitmask

// ---------------------------------------------------------------------------
// Baseline-ISA helpers (sm_80-era: survive the harness's plain sm_103 target)
// ---------------------------------------------------------------------------
__device__ __forceinline__ uint32_t smem_u32(const void* p) {
    uint32_t a;
    asm("{ .reg .u64 t; cvta.to.shared.u64 t, %1; cvt.u32.u64 %0, t; }" : "=r"(a) : "l"(p));
    return a;
}
__device__ __forceinline__ void ldsm_x4(uint32_t& r0, uint32_t& r1, uint32_t& r2,
                                        uint32_t& r3, uint32_t addr) {
    asm volatile("ldmatrix.sync.aligned.m8n8.x4.shared.b16 {%0,%1,%2,%3}, [%4];"
                 : "=r"(r0), "=r"(r1), "=r"(r2), "=r"(r3) : "r"(addr));
}
__device__ __forceinline__ void ldsm_x4t(uint32_t& r0, uint32_t& r1, uint32_t& r2,
                                         uint32_t& r3, uint32_t addr) {
    asm volatile("ldmatrix.sync.aligned.m8n8.x4.trans.shared.b16 {%0,%1,%2,%3}, [%4];"
                 : "=r"(r0), "=r"(r1), "=r"(r2), "=r"(r3) : "r"(addr));
}
__device__ __forceinline__ void mma_bf16(float* c, uint32_t a0, uint32_t a1, uint32_t a2,
                                         uint32_t a3, uint32_t b0, uint32_t b1) {
    asm volatile("mma.sync.aligned.m16n8k16.row.col.f32.bf16.bf16.f32 "
                 "{%0,%1,%2,%3}, {%4,%5,%6,%7}, {%8,%9}, {%0,%1,%2,%3};"
                 : "+f"(c[0]), "+f"(c[1]), "+f"(c[2]), "+f"(c[3])
                 : "r"(a0), "r"(a1), "r"(a2), "r"(a3), "r"(b0), "r"(b1));
}
__device__ __forceinline__ void mma_f16(float* c, uint32_t a0, uint32_t a1, uint32_t a2,
                                        uint32_t a3, uint32_t b0, uint32_t b1) {
    asm volatile("mma.sync.aligned.m16n8k16.row.col.f32.f16.f16.f32 "
                 "{%0,%1,%2,%3}, {%4,%5,%6,%7}, {%8,%9}, {%0,%1,%2,%3};"
                 : "+f"(c[0]), "+f"(c[1]), "+f"(c[2]), "+f"(c[3])
                 : "r"(a0), "r"(a1), "r"(a2), "r"(a3), "r"(b0), "r"(b1));
}
__device__ __forceinline__ void cpa16(uint32_t s, const void* g) {
    asm volatile("cp.async.cg.shared.global [%0], [%1], 16;" :: "r"(s), "l"(g));
}
#define CPA_COMMIT() asm volatile("cp.async.commit_group;" ::: "memory")
#define CPA_WAIT0()  asm volatile("cp.async.wait_group 0;" ::: "memory")

// bf16 pack/split (attention path — unchanged numerics)
__device__ __forceinline__ uint32_t pack2h(__nv_bfloat16 lo, __nv_bfloat16 hi) {
    return ((uint32_t)__bfloat16_as_ushort(hi) << 16) | __bfloat16_as_ushort(lo);
}
__device__ __forceinline__ void split2(float x, float y, uint32_t& hp, uint32_t& lp) {
    __nv_bfloat16 hx = __float2bfloat16(x), hy = __float2bfloat16(y);
    hp = pack2h(hx, hy);
    lp = pack2h(__float2bfloat16(x - __bfloat162float(hx)),
                __float2bfloat16(y - __bfloat162float(hy)));
}
// fp16 pack/split (GEMM path)
__device__ __forceinline__ uint32_t pack2f(__half lo, __half hi) {
    return ((uint32_t)__half_as_ushort(hi) << 16) | __half_as_ushort(lo);
}
__device__ __forceinline__ void split2h(float x, float y, uint32_t& hp, uint32_t& lp) {
    __half hx = __float2half_rn(x), hy = __float2half_rn(y);
    hp = pack2f(hx, hy);
    lp = pack2f(__float2half_rn(x - __half2float(hx)),
                __float2half_rn(y - __half2float(hy)));
}

// ---------------------------------------------------------------------------
// fp32 -> fp16 hi/lo split (inputs / ctx)
// ---------------------------------------------------------------------------
__global__ __launch_bounds__(256) void cvt_kernel(
    const float* __restrict__ src, __half* __restrict__ hi,
    __half* __restrict__ lo, int n4)
{
    int i = blockIdx.x * 256 + threadIdx.x;
    if (i >= n4) return;
    float4 v = ((const float4*)src)[i];
    uint32_t h0, l0, h1, l1;
    split2h(v.x, v.y, h0, l0);
    split2h(v.z, v.w, h1, l1);
    ((uint2*)hi)[i] = make_uint2(h0, h1);
    ((uint2*)lo)[i] = make_uint2(l0, l1);
}

// All 4 weight matrices -> fp16 hi only (lo term dropped in 2-product GEMM)
__global__ __launch_bounds__(256) void cvt_w_kernel(
    const float* __restrict__ w0, const float* __restrict__ w1,
    const float* __restrict__ w2, const float* __restrict__ w3)
{
    int z = blockIdx.z;
    const float* src = (z == 0) ? w0 : (z == 1) ? w1 : (z == 2) ? w2 : w3;
    __half* hi = g_wh + (size_t)z * WSZ;
    int i = blockIdx.x * 256 + threadIdx.x;
    if (i >= WSZ / 4) return;
    float4 v = ((const float4*)src)[i];
    uint32_t h0 = pack2f(__float2half_rn(v.x), __float2half_rn(v.y));
    uint32_t h1 = pack2f(__float2half_rn(v.z), __float2half_rn(v.w));
    ((uint2*)hi)[i] = make_uint2(h0, h1);
}

// mask (fp32, !=0 means masked) -> bitmask words
__global__ __launch_bounds__(256) void maskbits_kernel(const float* __restrict__ mask, int nwords)
{
    int gw = (blockIdx.x * blockDim.x + threadIdx.x) >> 5;
    int lane = threadIdx.x & 31;
    int nw = (gridDim.x * blockDim.x) >> 5;
    for (int w = gw; w < nwords; w += nw) {
        float v = mask[(size_t)w * 32 + lane];
        uint32_t bits = __ballot_sync(0xffffffffu, v != 0.f);
        if (lane == 0) g_mbits[w] = bits;
    }
}

// ---------------------------------------------------------------------------
// fp16 2-product GEMM via mma.sync: C = A @ W^T + bias
//   C ≈ Ah·Wh + Al·Wh  (A to 22 bits, W to 11 bits; dropped Ah·Wl ~2^-12 rel)
// block 128x128, 256 threads / 8 warps (warp tile 32x64), KC=32, 2 blocks/SM.
// ---------------------------------------------------------------------------
#define GKC 32
#define GROWB 80
#define SAR_B (128 * GROWB)            // 10240 (one array: 128 rows)
#define GSTAGE (3 * SAR_B)             // Ah,Al,Wh = 30720 per stage
#define GEMM_SMEM (2 * GSTAGE)         // 61440 -> 2 blocks/SM

template <bool QKV>
__global__ __launch_bounds__(256, 2) void mm_kernel(
    const __half* __restrict__ Ah, const __half* __restrict__ Al,
    const __half* __restrict__ Whb,
    const float* __restrict__ b0a, const float* __restrict__ b1a,
    const float* __restrict__ b2a, float* __restrict__ Cout)
{
    extern __shared__ char smem[];
    const uint32_t sb = smem_u32(smem);
    const int tid = threadIdx.x, lane = tid & 31, wid = tid >> 5;
    const int wm = wid & 3, wn = wid >> 2;          // 4x2 warp grid
    const int bm = blockIdx.y * 128, bn = blockIdx.x * 128;
    const int z = QKV ? blockIdx.z : 0;

    const __half* Bh = Whb + (size_t)z * WSZ;
    const float* bias = QKV ? ((z == 0) ? b0a : (z == 1) ? b1a : b2a) : b0a;

    float acc[2][8][4];
#pragma unroll
    for (int i = 0; i < 2; i++)
#pragma unroll
        for (int j = 0; j < 8; j++)
#pragma unroll
            for (int k = 0; k < 4; k++) acc[i][j][k] = 0.f;

    auto load_chunk = [&](int c, int st) {
        uint32_t dst = sb + st * GSTAGE;
        int k0 = c * GKC;
        const __half* srcs[3] = {Ah, Al, Bh};
#pragma unroll
        for (int arr = 0; arr < 3; arr++) {
            int rb = (arr < 2) ? bm : bn;
#pragma unroll
            for (int it = 0; it < 2; it++) {
                int idx = tid + it * 256;       // 0..511
                int r = idx >> 2, cc = idx & 3;
                cpa16(dst + arr * SAR_B + r * GROWB + cc * 16,
                      srcs[arr] + (size_t)(rb + r) * DMODEL + k0 + cc * 8);
            }
        }
        CPA_COMMIT();
    };

    load_chunk(0, 0);
    CPA_WAIT0();
    __syncthreads();

    const int m4 = lane >> 3;            // ldsm matrix id 0..3
    const int half_ = m4 & 1, sub = m4 >> 1;

    for (int c = 0; c < DMODEL / GKC; ++c) {
        int st = c & 1;
        if (c < DMODEL / GKC - 1) load_chunk(c + 1, st ^ 1);
        uint32_t base = sb + st * GSTAGE;

#pragma unroll
        for (int ks = 0; ks < 2; ks++) {
            // A fragments for this ks (hi+lo, both mf)
            uint32_t ah[2][4], al[2][4];
#pragma unroll
            for (int mf = 0; mf < 2; mf++) {
                uint32_t row = wm * 32 + mf * 16 + (lane & 15);
                uint32_t col = ks * 32 + ((lane >> 4) << 4);
                ldsm_x4(ah[mf][0], ah[mf][1], ah[mf][2], ah[mf][3],
                        base + 0 * SAR_B + row * GROWB + col);
                ldsm_x4(al[mf][0], al[mf][1], al[mf][2], al[mf][3],
                        base + 1 * SAR_B + row * GROWB + col);
            }
            // Two groups of 4 nf: load Wh pairs, round-robin 8 accumulators
#pragma unroll
            for (int hg = 0; hg < 2; hg++) {
                uint32_t bh[4][2];
#pragma unroll
                for (int g = 0; g < 2; g++) {
                    uint32_t row = wn * 64 + (hg * 4 + g * 2 + sub) * 8 + (lane & 7);
                    uint32_t ad = base + 2 * SAR_B + row * GROWB + ks * 32 + half_ * 16;
                    ldsm_x4(bh[g * 2][0], bh[g * 2][1], bh[g * 2 + 1][0], bh[g * 2 + 1][1], ad);
                }
#pragma unroll
                for (int p = 0; p < 2; p++)
#pragma unroll
                    for (int mf = 0; mf < 2; mf++)
#pragma unroll
                        for (int nf = 0; nf < 4; nf++) {
                            const uint32_t* A = (p == 0) ? ah[mf] : al[mf];
                            mma_f16(acc[mf][hg * 4 + nf], A[0], A[1], A[2], A[3],
                                    bh[nf][0], bh[nf][1]);
                        }
            }
        }
        if (c < DMODEL / GKC - 1) CPA_WAIT0();
        __syncthreads();
    }

    const int q4 = lane & 3, r4 = lane >> 2;
#pragma unroll
    for (int mf = 0; mf < 2; mf++)
#pragma unroll
        for (int nf = 0; nf < 8; nf++) {
            int col = bn + wn * 64 + nf * 8 + q4 * 2;
            float2 bb = *(const float2*)(bias + col);
#pragma unroll
            for (int hh = 0; hh < 2; hh++) {
                int row = bm + wm * 32 + mf * 16 + r4 + hh * 8;
                float v0 = acc[mf][nf][2 * hh + 0] + bb.x;
                float v1 = acc[mf][nf][2 * hh + 1] + bb.y;
                if (!QKV) {
                    *(float2*)(Cout + (size_t)row * DMODEL + col) = make_float2(v0, v1);
                } else {
                    int b = row >> 10, s = row & 1023, hd = col >> 6, d = col & 63;
                    size_t o = ((size_t)((b * NHEAD + hd) * SLEN + s)) * DKV + d;
                    uint32_t hp, lp;
                    split2(v0, v1, hp, lp);   // q/k/v stay bf16 hi/lo for attention
                    __nv_bfloat16* dh = (z == 0) ? g_qh : (z == 1) ? g_kh : g_vh;
                    __nv_bfloat16* dl = (z == 0) ? g_ql : (z == 1) ? g_kl : g_vl;
                    *(uint32_t*)(dh + o) = hp;
                    *(uint32_t*)(dl + o) = lp;
                }
            }
        }
}

// ---------------------------------------------------------------------------
// Flash attention via mma.sync, bf16 hi/lo 3-split (numerics unchanged).
// Block: 64 q-rows x one (b,h). 4 warps. Epilogue now writes ctx as fp16 hi/lo.
// ---------------------------------------------------------------------------
#define AROWB 144
#define AT_BYTES (64 * AROWB)        // 9216
#define ABUF (4 * AT_BYTES)          // Kh,Kl,Vh,Vl = 36864 per stage
#define ATTN_SMEM (2 * ABUF)         // 73728

__global__ __launch_bounds__(128) void attn_kernel()
{
    extern __shared__ char smem[];
    const uint32_t sb = smem_u32(smem);
    const int tid = threadIdx.x, lane = tid & 31, w = tid >> 5;
    const int q4 = lane & 3, r4 = lane >> 2;
    const int qt = blockIdx.x, bh = blockIdx.y;
    const int b = bh >> 3, h = bh & 7;

    const __nv_bfloat16* Qh = g_qh + (size_t)bh * SLEN * DKV + (size_t)qt * 64 * DKV;
    const __nv_bfloat16* Ql = g_ql + (size_t)bh * SLEN * DKV + (size_t)qt * 64 * DKV;
    const __nv_bfloat16* Kh = g_kh + (size_t)bh * SLEN * DKV;
    const __nv_bfloat16* Kl = g_kl + (size_t)bh * SLEN * DKV;
    const __nv_bfloat16* Vh = g_vh + (size_t)bh * SLEN * DKV;
    const __nv_bfloat16* Vl = g_vl + (size_t)bh * SLEN * DKV;

    // ---- stage Q into buffer 1 (arrays 0,1), extract fragments ----
    {
        uint32_t qb = sb + ABUF;
#pragma unroll
        for (int arr = 0; arr < 2; arr++) {
            const __nv_bfloat16* S = arr ? Ql : Qh;
#pragma unroll
            for (int it = 0; it < 4; it++) {
                int idx = tid + it * 128;      // 0..511
                int r = idx >> 3, cc = idx & 7;
                cpa16(qb + arr * AT_BYTES + r * AROWB + cc * 16, S + r * DKV + cc * 8);
            }
        }
        CPA_COMMIT();
        CPA_WAIT0();
        __syncthreads();
    }
    uint32_t qfh[4][4], qfl[4][4];
    {
        uint32_t qb = sb + ABUF;
        uint32_t row = w * 16 + (lane & 15);
#pragma unroll
        for (int ks = 0; ks < 4; ks++) {
            uint32_t col = ks * 32 + ((lane >> 4) << 4);
            ldsm_x4(qfh[ks][0], qfh[ks][1], qfh[ks][2], qfh[ks][3],
                    qb + 0 * AT_BYTES + row * AROWB + col);
            ldsm_x4(qfl[ks][0], qfl[ks][1], qfl[ks][2], qfl[ks][3],
                    qb + 1 * AT_BYTES + row * AROWB + col);
        }
    }

    auto load_tile = [&](int kt, int st) {
        uint32_t dst = sb + st * ABUF;
        const __nv_bfloat16* srcs[4] = {Kh + (size_t)kt * 64 * DKV, Kl + (size_t)kt * 64 * DKV,
                                        Vh + (size_t)kt * 64 * DKV, Vl + (size_t)kt * 64 * DKV};
#pragma unroll
        for (int arr = 0; arr < 4; arr++)
#pragma unroll
            for (int it = 0; it < 4; it++) {
                int idx = tid + it * 128;
                int r = idx >> 3, cc = idx & 7;
                cpa16(dst + arr * AT_BYTES + r * AROWB + cc * 16, srcs[arr] + r * DKV + cc * 8);
            }
        CPA_COMMIT();
    };

    load_tile(0, 0);     // buffer 0 (Q lives in buffer 1; disjoint)
    CPA_WAIT0();
    __syncthreads();     // orders Q-frag reads before tile 1 overwrites buf 1

    float o[8][4];
#pragma unroll
    for (int j = 0; j < 8; j++)
#pragma unroll
        for (int k = 0; k < 4; k++) o[j][k] = 0.f;
    float m0 = -1e30f, m1 = -1e30f, l0 = 0.f, l1 = 0.f;

    const uint32_t* mrow0 = g_mbits + ((size_t)b * SLEN + qt * 64 + w * 16 + r4) * 32;
    const uint32_t* mrow1 = mrow0 + 8 * 32;

    const int m4 = lane >> 3, half_ = m4 & 1, sub = m4 >> 1;

    for (int kt = 0; kt < 16; ++kt) {
        int st = kt & 1;
        if (kt < 15) load_tile(kt + 1, st ^ 1);
        uint32_t base = sb + st * ABUF;

        // ---- S = Q @ K^T: per ks load all 8 K-pairs, round-robin 8 accs ----
        float s[8][4];
#pragma unroll
        for (int j = 0; j < 8; j++)
#pragma unroll
            for (int k = 0; k < 4; k++) s[j][k] = 0.f;

#pragma unroll
        for (int ks = 0; ks < 4; ks++) {
            uint32_t kh[8][2], kl[8][2];
#pragma unroll
            for (int g = 0; g < 4; g++) {
                uint32_t row = (g * 2 + sub) * 8 + (lane & 7);
                uint32_t ad = base + row * AROWB + ks * 32 + half_ * 16;
                ldsm_x4(kh[g * 2][0], kh[g * 2][1], kh[g * 2 + 1][0], kh[g * 2 + 1][1], ad);
                ldsm_x4(kl[g * 2][0], kl[g * 2][1], kl[g * 2 + 1][0], kl[g * 2 + 1][1],
                        ad + AT_BYTES);
            }
#pragma unroll
            for (int p = 0; p < 3; p++)
#pragma unroll
                for (int nf = 0; nf < 8; nf++) {
                    const uint32_t* A = (p < 2) ? qfh[ks] : qfl[ks];
                    const uint32_t* B = (p == 1) ? kl[nf] : kh[nf];
                    mma_bf16(s[nf], A[0], A[1], A[2], A[3], B[0], B[1]);
                }
        }

        // ---- mask + scale ----
        uint32_t w0a = mrow0[kt * 2], w0b = mrow0[kt * 2 + 1];
        uint32_t w1a = mrow1[kt * 2], w1b = mrow1[kt * 2 + 1];
        float rm0 = -CUDART_INF_F, rm1 = -CUDART_INF_F;
#pragma unroll
        for (int nf = 0; nf < 8; nf++) {
            int c = nf * 8 + q4 * 2;
            uint32_t wr0 = (c < 32) ? w0a : w0b;
            uint32_t wr1 = (c < 32) ? w1a : w1b;
            int sh = c & 31;
            s[nf][0] = ((wr0 >> sh) & 1) ? -CUDART_INF_F : s[nf][0] * 0.125f;
            s[nf][1] = ((wr0 >> (sh + 1)) & 1) ? -CUDART_INF_F : s[nf][1] * 0.125f;
            s[nf][2] = ((wr1 >> sh) & 1) ? -CUDART_INF_F : s[nf][2] * 0.125f;
            s[nf][3] = ((wr1 >> (sh + 1)) & 1) ? -CUDART_INF_F : s[nf][3] * 0.125f;
            rm0 = fmaxf(rm0, fmaxf(s[nf][0], s[nf][1]));
            rm1 = fmaxf(rm1, fmaxf(s[nf][2], s[nf][3]));
        }
        rm0 = fmaxf(rm0, __shfl_xor_sync(0xffffffffu, rm0, 1));
        rm0 = fmaxf(rm0, __shfl_xor_sync(0xffffffffu, rm0, 2));
        rm1 = fmaxf(rm1, __shfl_xor_sync(0xffffffffu, rm1, 1));
        rm1 = fmaxf(rm1, __shfl_xor_sync(0xffffffffu, rm1, 2));

        float mn0 = fmaxf(m0, rm0), mn1 = fmaxf(m1, rm1);
        float sc0 = __expf(m0 - mn0), sc1 = __expf(m1 - mn1);
        float rs0 = 0.f, rs1 = 0.f;
        uint32_t pH01[8], pH23[8], pL01[8], pL23[8];
#pragma unroll
        for (int nf = 0; nf < 8; nf++) {
            float p0 = __expf(s[nf][0] - mn0);
            float p1 = __expf(s[nf][1] - mn0);
            float p2 = __expf(s[nf][2] - mn1);
            float p3 = __expf(s[nf][3] - mn1);
            rs0 += p0 + p1;
            rs1 += p2 + p3;
            split2(p0, p1, pH01[nf], pL01[nf]);
            split2(p2, p3, pH23[nf], pL23[nf]);
        }
        rs0 += __shfl_xor_sync(0xffffffffu, rs0, 1);
        rs0 += __shfl_xor_sync(0xffffffffu, rs0, 2);
        rs1 += __shfl_xor_sync(0xffffffffu, rs1, 1);
        rs1 += __shfl_xor_sync(0xffffffffu, rs1, 2);
        l0 = l0 * sc0 + rs0;
        l1 = l1 * sc1 + rs1;
        m0 = mn0;
        m1 = mn1;
#pragma unroll
        for (int nf = 0; nf < 8; nf++) {
            o[nf][0] *= sc0;
            o[nf][1] *= sc0;
            o[nf][2] *= sc1;
            o[nf][3] *= sc1;
        }

        // ---- O += P @ V: per ks hoist all V-pairs, round-robin 8 accs ----
#pragma unroll
        for (int ks = 0; ks < 4; ks++) {
            uint32_t a0 = pH01[2 * ks], a1 = pH23[2 * ks];
            uint32_t a2 = pH01[2 * ks + 1], a3 = pH23[2 * ks + 1];
            uint32_t la0 = pL01[2 * ks], la1 = pL23[2 * ks];
            uint32_t la2 = pL01[2 * ks + 1], la3 = pL23[2 * ks + 1];
            uint32_t vaddr = (ks * 16 + (lane & 15)) * AROWB + ((lane >> 4) << 4);
            uint32_t vh[16], vl[16];
#pragma unroll
            for (int nf2 = 0; nf2 < 4; nf2++) {
                ldsm_x4t(vh[nf2 * 4 + 0], vh[nf2 * 4 + 1], vh[nf2 * 4 + 2], vh[nf2 * 4 + 3],
                         base + 2 * AT_BYTES + vaddr + nf2 * 32);
                ldsm_x4t(vl[nf2 * 4 + 0], vl[nf2 * 4 + 1], vl[nf2 * 4 + 2], vl[nf2 * 4 + 3],
                         base + 3 * AT_BYTES + vaddr + nf2 * 32);
            }
#pragma unroll
            for (int p = 0; p < 3; p++)
#pragma unroll
                for (int j = 0; j < 8; j++) {
                    if (p == 0)      mma_bf16(o[j], a0, a1, a2, a3, vh[2 * j], vh[2 * j + 1]);
                    else if (p == 1) mma_bf16(o[j], a0, a1, a2, a3, vl[2 * j], vl[2 * j + 1]);
                    else             mma_bf16(o[j], la0, la1, la2, la3, vh[2 * j], vh[2 * j + 1]);
                }
        }

        if (kt < 15) CPA_WAIT0();
        __syncthreads();
    }

    // ---- epilogue: ctx = O / l -> fp16 hi/lo into g_ah/g_al ----
    float il0 = (l0 > 0.f) ? (1.f / l0) : 0.f;
    float il1 = (l1 > 0.f) ? (1.f / l1) : 0.f;
    int row0 = qt * 64 + w * 16 + r4;
#pragma unroll
    for (int nf = 0; nf < 8; nf++) {
        int col = h * 64 + nf * 8 + q4 * 2;
        uint32_t hp, lp;
        split2h(o[nf][0] * il0, o[nf][1] * il0, hp, lp);
        *(uint32_t*)(g_ah + (size_t)(b * SLEN + row0) * DMODEL + col) = hp;
        *(uint32_t*)(g_al + (size_t)(b * SLEN + row0) * DMODEL + col) = lp;
        split2h(o[nf][2] * il1, o[nf][3] * il1, hp, lp);
        *(uint32_t*)(g_ah + (size_t)(b * SLEN + row0 + 8) * DMODEL + col) = hp;
        *(uint32_t*)(g_al + (size_t)(b * SLEN + row0 + 8) * DMODEL + col) = lp;
    }
}

// ---------------------------------------------------------------------------
extern "C" void kernel_launch(void* const* d_in, const int* in_sizes, int n_in,
                              void* d_out, int out_size)
{
    const float* inputs = (const float*)d_in[0];
    const float* mask   = (const float*)d_in[1];
    const float* wq = (const float*)d_in[2];
    const float* bq = (const float*)d_in[3];
    const float* wk = (const float*)d_in[4];
    const float* bk = (const float*)d_in[5];
    const float* wv = (const float*)d_in[6];
    const float* bv = (const float*)d_in[7];
    const float* wo = (const float*)d_in[8];
    const float* bo = (const float*)d_in[9];
    float* out = (float*)d_out;

    __half *ah, *al, *wh;
    cudaGetSymbolAddress((void**)&ah, g_ah);
    cudaGetSymbolAddress((void**)&al, g_al);
    cudaGetSymbolAddress((void**)&wh, g_wh);

    cvt_kernel<<<(MROWS * DMODEL / 4 + 255) / 256, 256>>>(inputs, ah, al, MROWS * DMODEL / 4);
    cvt_w_kernel<<<dim3((WSZ / 4 + 255) / 256, 1, 4), 256>>>(wq, wk, wv, wo);
    maskbits_kernel<<<256, 256>>>(mask, BATCH * SLEN * (SLEN / 32));

    cudaFuncSetAttribute(mm_kernel<true>, cudaFuncAttributeMaxDynamicSharedMemorySize, GEMM_SMEM);
    cudaFuncSetAttribute(mm_kernel<false>, cudaFuncAttributeMaxDynamicSharedMemorySize, GEMM_SMEM);
    cudaFuncSetAttribute(attn_kernel, cudaFuncAttributeMaxDynamicSharedMemorySize, ATTN_SMEM);

    dim3 gqkv(DMODEL / 128, MROWS / 128, 3);   // (4, 64, 3)
    mm_kernel<true><<<gqkv, 256, GEMM_SMEM>>>(ah, al, wh, bq, bk, bv, nullptr);

    dim3 ga(SLEN / 64, BATCH * NHEAD);         // (16, 64)
    attn_kernel<<<ga, 128, ATTN_SMEM>>>();     // writes ctx fp16 hi/lo into g_ah/g_al

    dim3 go(DMODEL / 128, MROWS / 128);        // (4, 64)
    mm_kernel<false><<<go, 256, GEMM_SMEM>>>(ah, al, wh + 3 * WSZ,
                                             bo, nullptr, nullptr, out);
}

// round 10
// speedup vs baseline: 1.6089x; 1.1178x over previous
#include <cuda_runtime.h>
#include <cuda_fp16.h>
#include <math_constants.h>
#include <cstdint>

#define BATCH  8
#define SLEN   1024
#define NHEAD  8
#define DMODEL 512
#define DKV    64
#define MROWS  (BATCH * SLEN)   // 8192
#define WSZ    (DMODEL * DMODEL)

// ---------------------------------------------------------------------------
// Scratch (allocation-free: __device__ globals) — all fp16 now
// ---------------------------------------------------------------------------
__device__ __half g_ah[MROWS * DMODEL];     // A hi (inputs, later ctx)
__device__ __half g_al[MROWS * DMODEL];     // A lo
__device__ __half g_wh[4 * WSZ];            // wq|wk|wv|wo hi (lo dropped)
__device__ __half g_qh[MROWS * DMODEL], g_ql[MROWS * DMODEL];  // [b,h,s,d]
__device__ __half g_kh[MROWS * DMODEL];     // K hi only
__device__ __half g_vh[MROWS * DMODEL];     // V hi only
__device__ uint32_t g_mbits[BATCH * SLEN * (SLEN / 32)];   // 1MB bitmask

// ---------------------------------------------------------------------------
// Baseline-ISA helpers
// ---------------------------------------------------------------------------
__device__ __forceinline__ uint32_t smem_u32(const void* p) {
    uint32_t a;
    asm("{ .reg .u64 t; cvta.to.shared.u64 t, %1; cvt.u32.u64 %0, t; }" : "=r"(a) : "l"(p));
    return a;
}
__device__ __forceinline__ void ldsm_x4(uint32_t& r0, uint32_t& r1, uint32_t& r2,
                                        uint32_t& r3, uint32_t addr) {
    asm volatile("ldmatrix.sync.aligned.m8n8.x4.shared.b16 {%0,%1,%2,%3}, [%4];"
                 : "=r"(r0), "=r"(r1), "=r"(r2), "=r"(r3) : "r"(addr));
}
__device__ __forceinline__ void ldsm_x4t(uint32_t& r0, uint32_t& r1, uint32_t& r2,
                                         uint32_t& r3, uint32_t addr) {
    asm volatile("ldmatrix.sync.aligned.m8n8.x4.trans.shared.b16 {%0,%1,%2,%3}, [%4];"
                 : "=r"(r0), "=r"(r1), "=r"(r2), "=r"(r3) : "r"(addr));
}
__device__ __forceinline__ void mma_f16(float* c, uint32_t a0, uint32_t a1, uint32_t a2,
                                        uint32_t a3, uint32_t b0, uint32_t b1) {
    asm volatile("mma.sync.aligned.m16n8k16.row.col.f32.f16.f16.f32 "
                 "{%0,%1,%2,%3}, {%4,%5,%6,%7}, {%8,%9}, {%0,%1,%2,%3};"
                 : "+f"(c[0]), "+f"(c[1]), "+f"(c[2]), "+f"(c[3])
                 : "r"(a0), "r"(a1), "r"(a2), "r"(a3), "r"(b0), "r"(b1));
}
__device__ __forceinline__ void cpa16(uint32_t s, const void* g) {
    asm volatile("cp.async.cg.shared.global [%0], [%1], 16;" :: "r"(s), "l"(g));
}
#define CPA_COMMIT() asm volatile("cp.async.commit_group;" ::: "memory")
#define CPA_WAIT0()  asm volatile("cp.async.wait_group 0;" ::: "memory")

__device__ __forceinline__ uint32_t pack2f(__half lo, __half hi) {
    return ((uint32_t)__half_as_ushort(hi) << 16) | __half_as_ushort(lo);
}
__device__ __forceinline__ void split2h(float x, float y, uint32_t& hp, uint32_t& lp) {
    __half hx = __float2half_rn(x), hy = __float2half_rn(y);
    hp = pack2f(hx, hy);
    lp = pack2f(__float2half_rn(x - __half2float(hx)),
                __float2half_rn(y - __half2float(hy)));
}

// ---------------------------------------------------------------------------
// fp32 -> fp16 hi/lo split (inputs / ctx)
// ---------------------------------------------------------------------------
__global__ __launch_bounds__(256) void cvt_kernel(
    const float* __restrict__ src, __half* __restrict__ hi,
    __half* __restrict__ lo, int n4)
{
    int i = blockIdx.x * 256 + threadIdx.x;
    if (i >= n4) return;
    float4 v = ((const float4*)src)[i];
    uint32_t h0, l0, h1, l1;
    split2h(v.x, v.y, h0, l0);
    split2h(v.z, v.w, h1, l1);
    ((uint2*)hi)[i] = make_uint2(h0, h1);
    ((uint2*)lo)[i] = make_uint2(l0, l1);
}

// All 4 weight matrices -> fp16 hi only
__global__ __launch_bounds__(256) void cvt_w_kernel(
    const float* __restrict__ w0, const float* __restrict__ w1,
    const float* __restrict__ w2, const float* __restrict__ w3)
{
    int z = blockIdx.z;
    const float* src = (z == 0) ? w0 : (z == 1) ? w1 : (z == 2) ? w2 : w3;
    __half* hi = g_wh + (size_t)z * WSZ;
    int i = blockIdx.x * 256 + threadIdx.x;
    if (i >= WSZ / 4) return;
    float4 v = ((const float4*)src)[i];
    uint32_t h0 = pack2f(__float2half_rn(v.x), __float2half_rn(v.y));
    uint32_t h1 = pack2f(__float2half_rn(v.z), __float2half_rn(v.w));
    ((uint2*)hi)[i] = make_uint2(h0, h1);
}

// mask (fp32, !=0 means masked) -> bitmask words
__global__ __launch_bounds__(256) void maskbits_kernel(const float* __restrict__ mask, int nwords)
{
    int gw = (blockIdx.x * blockDim.x + threadIdx.x) >> 5;
    int lane = threadIdx.x & 31;
    int nw = (gridDim.x * blockDim.x) >> 5;
    for (int w = gw; w < nwords; w += nw) {
        float v = mask[(size_t)w * 32 + lane];
        uint32_t bits = __ballot_sync(0xffffffffu, v != 0.f);
        if (lane == 0) g_mbits[w] = bits;
    }
}

// ---------------------------------------------------------------------------
// fp16 2-product GEMM via mma.sync: C ≈ Ah·Wh + Al·Wh + bias
// block 128x128, 256 threads / 8 warps (warp tile 32x64), KC=32, 2 blocks/SM.
// ---------------------------------------------------------------------------
#define GKC 32
#define GROWB 80
#define SAR_B (128 * GROWB)            // 10240
#define GSTAGE (3 * SAR_B)             // Ah,Al,Wh = 30720 per stage
#define GEMM_SMEM (2 * GSTAGE)         // 61440

template <bool QKV>
__global__ __launch_bounds__(256, 2) void mm_kernel(
    const __half* __restrict__ Ah, const __half* __restrict__ Al,
    const __half* __restrict__ Whb,
    const float* __restrict__ b0a, const float* __restrict__ b1a,
    const float* __restrict__ b2a, float* __restrict__ Cout)
{
    extern __shared__ char smem[];
    const uint32_t sb = smem_u32(smem);
    const int tid = threadIdx.x, lane = tid & 31, wid = tid >> 5;
    const int wm = wid & 3, wn = wid >> 2;
    const int bm = blockIdx.y * 128, bn = blockIdx.x * 128;
    const int z = QKV ? blockIdx.z : 0;

    const __half* Bh = Whb + (size_t)z * WSZ;
    const float* bias = QKV ? ((z == 0) ? b0a : (z == 1) ? b1a : b2a) : b0a;

    float acc[2][8][4];
#pragma unroll
    for (int i = 0; i < 2; i++)
#pragma unroll
        for (int j = 0; j < 8; j++)
#pragma unroll
            for (int k = 0; k < 4; k++) acc[i][j][k] = 0.f;

    auto load_chunk = [&](int c, int st) {
        uint32_t dst = sb + st * GSTAGE;
        int k0 = c * GKC;
        const __half* srcs[3] = {Ah, Al, Bh};
#pragma unroll
        for (int arr = 0; arr < 3; arr++) {
            int rb = (arr < 2) ? bm : bn;
#pragma unroll
            for (int it = 0; it < 2; it++) {
                int idx = tid + it * 256;
                int r = idx >> 2, cc = idx & 3;
                cpa16(dst + arr * SAR_B + r * GROWB + cc * 16,
                      srcs[arr] + (size_t)(rb + r) * DMODEL + k0 + cc * 8);
            }
        }
        CPA_COMMIT();
    };

    load_chunk(0, 0);
    CPA_WAIT0();
    __syncthreads();

    const int m4 = lane >> 3;
    const int half_ = m4 & 1, sub = m4 >> 1;

    for (int c = 0; c < DMODEL / GKC; ++c) {
        int st = c & 1;
        if (c < DMODEL / GKC - 1) load_chunk(c + 1, st ^ 1);
        uint32_t base = sb + st * GSTAGE;

#pragma unroll
        for (int ks = 0; ks < 2; ks++) {
            uint32_t ah[2][4], al[2][4];
#pragma unroll
            for (int mf = 0; mf < 2; mf++) {
                uint32_t row = wm * 32 + mf * 16 + (lane & 15);
                uint32_t col = ks * 32 + ((lane >> 4) << 4);
                ldsm_x4(ah[mf][0], ah[mf][1], ah[mf][2], ah[mf][3],
                        base + 0 * SAR_B + row * GROWB + col);
                ldsm_x4(al[mf][0], al[mf][1], al[mf][2], al[mf][3],
                        base + 1 * SAR_B + row * GROWB + col);
            }
#pragma unroll
            for (int hg = 0; hg < 2; hg++) {
                uint32_t bh[4][2];
#pragma unroll
                for (int g = 0; g < 2; g++) {
                    uint32_t row = wn * 64 + (hg * 4 + g * 2 + sub) * 8 + (lane & 7);
                    uint32_t ad = base + 2 * SAR_B + row * GROWB + ks * 32 + half_ * 16;
                    ldsm_x4(bh[g * 2][0], bh[g * 2][1], bh[g * 2 + 1][0], bh[g * 2 + 1][1], ad);
                }
#pragma unroll
                for (int p = 0; p < 2; p++)
#pragma unroll
                    for (int mf = 0; mf < 2; mf++)
#pragma unroll
                        for (int nf = 0; nf < 4; nf++) {
                            const uint32_t* A = (p == 0) ? ah[mf] : al[mf];
                            mma_f16(acc[mf][hg * 4 + nf], A[0], A[1], A[2], A[3],
                                    bh[nf][0], bh[nf][1]);
                        }
            }
        }
        if (c < DMODEL / GKC - 1) CPA_WAIT0();
        __syncthreads();
    }

    const int q4 = lane & 3, r4 = lane >> 2;
#pragma unroll
    for (int mf = 0; mf < 2; mf++)
#pragma unroll
        for (int nf = 0; nf < 8; nf++) {
            int col = bn + wn * 64 + nf * 8 + q4 * 2;
            float2 bb = *(const float2*)(bias + col);
#pragma unroll
            for (int hh = 0; hh < 2; hh++) {
                int row = bm + wm * 32 + mf * 16 + r4 + hh * 8;
                float v0 = acc[mf][nf][2 * hh + 0] + bb.x;
                float v1 = acc[mf][nf][2 * hh + 1] + bb.y;
                if (!QKV) {
                    *(float2*)(Cout + (size_t)row * DMODEL + col) = make_float2(v0, v1);
                } else {
                    int b = row >> 10, s = row & 1023, hd = col >> 6, d = col & 63;
                    size_t o = ((size_t)((b * NHEAD + hd) * SLEN + s)) * DKV + d;
                    uint32_t hp, lp;
                    split2h(v0, v1, hp, lp);
                    if (z == 0) {              // Q: hi + lo (22-bit)
                        *(uint32_t*)(g_qh + o) = hp;
                        *(uint32_t*)(g_ql + o) = lp;
                    } else if (z == 1) {       // K: hi only
                        *(uint32_t*)(g_kh + o) = hp;
                    } else {                   // V: hi only
                        *(uint32_t*)(g_vh + o) = hp;
                    }
                }
            }
        }
}

// ---------------------------------------------------------------------------
// Flash attention via fp16 mma.sync, 2-product split on QK^T and PV.
// Block: 64 q-rows x one (b,h). 4 warps. smem stage = Kh,Vh only (18KB).
// ---------------------------------------------------------------------------
#define AROWB 144
#define AT_BYTES (64 * AROWB)        // 9216
#define ABUF (2 * AT_BYTES)          // Kh,Vh = 18432 per stage
#define ATTN_SMEM (2 * ABUF)         // 36864

__global__ __launch_bounds__(128) void attn_kernel()
{
    extern __shared__ char smem[];
    const uint32_t sb = smem_u32(smem);
    const int tid = threadIdx.x, lane = tid & 31, w = tid >> 5;
    const int q4 = lane & 3, r4 = lane >> 2;
    const int qt = blockIdx.x, bh = blockIdx.y;
    const int b = bh >> 3, h = bh & 7;

    const __half* Qh = g_qh + (size_t)bh * SLEN * DKV + (size_t)qt * 64 * DKV;
    const __half* Ql = g_ql + (size_t)bh * SLEN * DKV + (size_t)qt * 64 * DKV;
    const __half* Kh = g_kh + (size_t)bh * SLEN * DKV;
    const __half* Vh = g_vh + (size_t)bh * SLEN * DKV;

    // ---- stage Q (hi,lo) into buffer 1, extract fragments ----
    {
        uint32_t qb = sb + ABUF;
#pragma unroll
        for (int arr = 0; arr < 2; arr++) {
            const __half* S = arr ? Ql : Qh;
#pragma unroll
            for (int it = 0; it < 4; it++) {
                int idx = tid + it * 128;      // 0..511
                int r = idx >> 3, cc = idx & 7;
                cpa16(qb + arr * AT_BYTES + r * AROWB + cc * 16, S + r * DKV + cc * 8);
            }
        }
        CPA_COMMIT();
        CPA_WAIT0();
        __syncthreads();
    }
    uint32_t qfh[4][4], qfl[4][4];
    {
        uint32_t qb = sb + ABUF;
        uint32_t row = w * 16 + (lane & 15);
#pragma unroll
        for (int ks = 0; ks < 4; ks++) {
            uint32_t col = ks * 32 + ((lane >> 4) << 4);
            ldsm_x4(qfh[ks][0], qfh[ks][1], qfh[ks][2], qfh[ks][3],
                    qb + 0 * AT_BYTES + row * AROWB + col);
            ldsm_x4(qfl[ks][0], qfl[ks][1], qfl[ks][2], qfl[ks][3],
                    qb + 1 * AT_BYTES + row * AROWB + col);
        }
    }

    auto load_tile = [&](int kt, int st) {
        uint32_t dst = sb + st * ABUF;
        const __half* srcs[2] = {Kh + (size_t)kt * 64 * DKV, Vh + (size_t)kt * 64 * DKV};
#pragma unroll
        for (int arr = 0; arr < 2; arr++)
#pragma unroll
            for (int it = 0; it < 4; it++) {
                int idx = tid + it * 128;
                int r = idx >> 3, cc = idx & 7;
                cpa16(dst + arr * AT_BYTES + r * AROWB + cc * 16, srcs[arr] + r * DKV + cc * 8);
            }
        CPA_COMMIT();
    };

    load_tile(0, 0);     // buffer 0 (Q lives in buffer 1; disjoint)
    CPA_WAIT0();
    __syncthreads();     // orders Q-frag reads before tile 1 overwrites buf 1

    float o[8][4];
#pragma unroll
    for (int j = 0; j < 8; j++)
#pragma unroll
        for (int k = 0; k < 4; k++) o[j][k] = 0.f;
    float m0 = -1e30f, m1 = -1e30f, l0 = 0.f, l1 = 0.f;

    const uint32_t* mrow0 = g_mbits + ((size_t)b * SLEN + qt * 64 + w * 16 + r4) * 32;
    const uint32_t* mrow1 = mrow0 + 8 * 32;

    const int m4 = lane >> 3, half_ = m4 & 1, sub = m4 >> 1;

    for (int kt = 0; kt < 16; ++kt) {
        int st = kt & 1;
        if (kt < 15) load_tile(kt + 1, st ^ 1);
        uint32_t base = sb + st * ABUF;

        // ---- S = Q @ K^T: 2 products (Qh·Kh + Ql·Kh), 8 accumulators ----
        float s[8][4];
#pragma unroll
        for (int j = 0; j < 8; j++)
#pragma unroll
            for (int k = 0; k < 4; k++) s[j][k] = 0.f;

#pragma unroll
        for (int ks = 0; ks < 4; ks++) {
            uint32_t kh[8][2];
#pragma unroll
            for (int g = 0; g < 4; g++) {
                uint32_t row = (g * 2 + sub) * 8 + (lane & 7);
                uint32_t ad = base + row * AROWB + ks * 32 + half_ * 16;
                ldsm_x4(kh[g * 2][0], kh[g * 2][1], kh[g * 2 + 1][0], kh[g * 2 + 1][1], ad);
            }
#pragma unroll
            for (int p = 0; p < 2; p++)
#pragma unroll
                for (int nf = 0; nf < 8; nf++) {
                    const uint32_t* A = (p == 0) ? qfh[ks] : qfl[ks];
                    mma_f16(s[nf], A[0], A[1], A[2], A[3], kh[nf][0], kh[nf][1]);
                }
        }

        // ---- mask + scale ----
        uint32_t w0a = mrow0[kt * 2], w0b = mrow0[kt * 2 + 1];
        uint32_t w1a = mrow1[kt * 2], w1b = mrow1[kt * 2 + 1];
        float rm0 = -CUDART_INF_F, rm1 = -CUDART_INF_F;
#pragma unroll
        for (int nf = 0; nf < 8; nf++) {
            int c = nf * 8 + q4 * 2;
            uint32_t wr0 = (c < 32) ? w0a : w0b;
            uint32_t wr1 = (c < 32) ? w1a : w1b;
            int sh = c & 31;
            s[nf][0] = ((wr0 >> sh) & 1) ? -CUDART_INF_F : s[nf][0] * 0.125f;
            s[nf][1] = ((wr0 >> (sh + 1)) & 1) ? -CUDART_INF_F : s[nf][1] * 0.125f;
            s[nf][2] = ((wr1 >> sh) & 1) ? -CUDART_INF_F : s[nf][2] * 0.125f;
            s[nf][3] = ((wr1 >> (sh + 1)) & 1) ? -CUDART_INF_F : s[nf][3] * 0.125f;
            rm0 = fmaxf(rm0, fmaxf(s[nf][0], s[nf][1]));
            rm1 = fmaxf(rm1, fmaxf(s[nf][2], s[nf][3]));
        }
        rm0 = fmaxf(rm0, __shfl_xor_sync(0xffffffffu, rm0, 1));
        rm0 = fmaxf(rm0, __shfl_xor_sync(0xffffffffu, rm0, 2));
        rm1 = fmaxf(rm1, __shfl_xor_sync(0xffffffffu, rm1, 1));
        rm1 = fmaxf(rm1, __shfl_xor_sync(0xffffffffu, rm1, 2));

        float mn0 = fmaxf(m0, rm0), mn1 = fmaxf(m1, rm1);
        float sc0 = __expf(m0 - mn0), sc1 = __expf(m1 - mn1);
        float rs0 = 0.f, rs1 = 0.f;
        uint32_t pH01[8], pH23[8], pL01[8], pL23[8];
#pragma unroll
        for (int nf = 0; nf < 8; nf++) {
            float p0 = __expf(s[nf][0] - mn0);
            float p1 = __expf(s[nf][1] - mn0);
            float p2 = __expf(s[nf][2] - mn1);
            float p3 = __expf(s[nf][3] - mn1);
            rs0 += p0 + p1;
            rs1 += p2 + p3;
            split2h(p0, p1, pH01[nf], pL01[nf]);
            split2h(p2, p3, pH23[nf], pL23[nf]);
        }
        rs0 += __shfl_xor_sync(0xffffffffu, rs0, 1);
        rs0 += __shfl_xor_sync(0xffffffffu, rs0, 2);
        rs1 += __shfl_xor_sync(0xffffffffu, rs1, 1);
        rs1 += __shfl_xor_sync(0xffffffffu, rs1, 2);
        l0 = l0 * sc0 + rs0;
        l1 = l1 * sc1 + rs1;
        m0 = mn0;
        m1 = mn1;
#pragma unroll
        for (int nf = 0; nf < 8; nf++) {
            o[nf][0] *= sc0;
            o[nf][1] *= sc0;
            o[nf][2] *= sc1;
            o[nf][3] *= sc1;
        }

        // ---- O += P @ V: 2 products (Ph·Vh + Pl·Vh), 8 accumulators ----
#pragma unroll
        for (int ks = 0; ks < 4; ks++) {
            uint32_t a0 = pH01[2 * ks], a1 = pH23[2 * ks];
            uint32_t a2 = pH01[2 * ks + 1], a3 = pH23[2 * ks + 1];
            uint32_t la0 = pL01[2 * ks], la1 = pL23[2 * ks];
            uint32_t la2 = pL01[2 * ks + 1], la3 = pL23[2 * ks + 1];
            uint32_t vaddr = (ks * 16 + (lane & 15)) * AROWB + ((lane >> 4) << 4);
            uint32_t vh[16];
#pragma unroll
            for (int nf2 = 0; nf2 < 4; nf2++) {
                ldsm_x4t(vh[nf2 * 4 + 0], vh[nf2 * 4 + 1], vh[nf2 * 4 + 2], vh[nf2 * 4 + 3],
                         base + 1 * AT_BYTES + vaddr + nf2 * 32);
            }
#pragma unroll
            for (int p = 0; p < 2; p++)
#pragma unroll
                for (int j = 0; j < 8; j++) {
                    if (p == 0) mma_f16(o[j], a0, a1, a2, a3, vh[2 * j], vh[2 * j + 1]);
                    else        mma_f16(o[j], la0, la1, la2, la3, vh[2 * j], vh[2 * j + 1]);
                }
        }

        if (kt < 15) CPA_WAIT0();
        __syncthreads();
    }

    // ---- epilogue: ctx = O / l -> fp16 hi/lo into g_ah/g_al ----
    float il0 = (l0 > 0.f) ? (1.f / l0) : 0.f;
    float il1 = (l1 > 0.f) ? (1.f / l1) : 0.f;
    int row0 = qt * 64 + w * 16 + r4;
#pragma unroll
    for (int nf = 0; nf < 8; nf++) {
        int col = h * 64 + nf * 8 + q4 * 2;
        uint32_t hp, lp;
        split2h(o[nf][0] * il0, o[nf][1] * il0, hp, lp);
        *(uint32_t*)(g_ah + (size_t)(b * SLEN + row0) * DMODEL + col) = hp;
        *(uint32_t*)(g_al + (size_t)(b * SLEN + row0) * DMODEL + col) = lp;
        split2h(o[nf][2] * il1, o[nf][3] * il1, hp, lp);
        *(uint32_t*)(g_ah + (size_t)(b * SLEN + row0 + 8) * DMODEL + col) = hp;
        *(uint32_t*)(g_al + (size_t)(b * SLEN + row0 + 8) * DMODEL + col) = lp;
    }
}

// ---------------------------------------------------------------------------
extern "C" void kernel_launch(void* const* d_in, const int* in_sizes, int n_in,
                              void* d_out, int out_size)
{
    const float* inputs = (const float*)d_in[0];
    const float* mask   = (const float*)d_in[1];
    const float* wq = (const float*)d_in[2];
    const float* bq = (const float*)d_in[3];
    const float* wk = (const float*)d_in[4];
    const float* bk = (const float*)d_in[5];
    const float* wv = (const float*)d_in[6];
    const float* bv = (const float*)d_in[7];
    const float* wo = (const float*)d_in[8];
    const float* bo = (const float*)d_in[9];
    float* out = (float*)d_out;

    __half *ah, *al, *wh;
    cudaGetSymbolAddress((void**)&ah, g_ah);
    cudaGetSymbolAddress((void**)&al, g_al);
    cudaGetSymbolAddress((void**)&wh, g_wh);

    cvt_kernel<<<(MROWS * DMODEL / 4 + 255) / 256, 256>>>(inputs, ah, al, MROWS * DMODEL / 4);
    cvt_w_kernel<<<dim3((WSZ / 4 + 255) / 256, 1, 4), 256>>>(wq, wk, wv, wo);
    maskbits_kernel<<<256, 256>>>(mask, BATCH * SLEN * (SLEN / 32));

    cudaFuncSetAttribute(mm_kernel<true>, cudaFuncAttributeMaxDynamicSharedMemorySize, GEMM_SMEM);
    cudaFuncSetAttribute(mm_kernel<false>, cudaFuncAttributeMaxDynamicSharedMemorySize, GEMM_SMEM);
    cudaFuncSetAttribute(attn_kernel, cudaFuncAttributeMaxDynamicSharedMemorySize, ATTN_SMEM);

    dim3 gqkv(DMODEL / 128, MROWS / 128, 3);   // (4, 64, 3)
    mm_kernel<true><<<gqkv, 256, GEMM_SMEM>>>(ah, al, wh, bq, bk, bv, nullptr);

    dim3 ga(SLEN / 64, BATCH * NHEAD);         // (16, 64)
    attn_kernel<<<ga, 128, ATTN_SMEM>>>();     // writes ctx fp16 hi/lo into g_ah/g_al

    dim3 go(DMODEL / 128, MROWS / 128);        // (4, 64)
    mm_kernel<false><<<go, 256, GEMM_SMEM>>>(ah, al, wh + 3 * WSZ,
                                             bo, nullptr, nullptr, out);
}